// round 13
// baseline (speedup 1.0000x reference)
#include <cuda_runtime.h>
#include <cuda_bf16.h>
#include <cstdint>

#define B_   2
#define T_   4096
#define D_   768
#define H_   12
#define HD_  64
#define SCALE_ 0.125f

#define QT 128
#define KT 64

// ---------------- scratch ----------------
__device__ __nv_bfloat16 g_qh[(size_t)B_ * H_ * T_ * HD_];   // [B,H,T,hd]
__device__ __nv_bfloat16 g_ql[(size_t)B_ * H_ * T_ * HD_];
__device__ __nv_bfloat16 g_kh[(size_t)B_ * H_ * T_ * HD_];
__device__ __nv_bfloat16 g_kl[(size_t)B_ * H_ * T_ * HD_];
__device__ __nv_bfloat16 g_vh[(size_t)B_ * H_ * T_ * HD_];   // TRANSPOSED: [B,H,hd,T]
__device__ __nv_bfloat16 g_vl[(size_t)B_ * H_ * T_ * HD_];
__device__ __nv_bfloat16 g_xh[(size_t)B_ * T_ * D_];
__device__ __nv_bfloat16 g_xl[(size_t)B_ * T_ * D_];
__device__ __nv_bfloat16 g_ah[(size_t)B_ * T_ * D_];
__device__ __nv_bfloat16 g_al[(size_t)B_ * T_ * D_];
__device__ __nv_bfloat16 g_wqh[(size_t)3 * D_ * D_];
__device__ __nv_bfloat16 g_wql[(size_t)3 * D_ * D_];
__device__ __nv_bfloat16 g_woh[(size_t)D_ * D_];
__device__ __nv_bfloat16 g_wol[(size_t)D_ * D_];

// ======================= helpers ========================
__device__ __forceinline__ uint32_t smem_u32(const void* p) {
    uint32_t a;
    asm("{ .reg .u64 t; cvta.to.shared.u64 t, %1; cvt.u32.u64 %0, t; }"
        : "=r"(a) : "l"(p));
    return a;
}

__device__ __forceinline__ void cp16(uint32_t s, const void* g) {
    asm volatile("cp.async.cg.shared.global [%0], [%1], 16;" :: "r"(s), "l"(g));
}
#define CP_COMMIT() asm volatile("cp.async.commit_group;" ::: "memory")
#define CP_WAIT2()  asm volatile("cp.async.wait_group 2;" ::: "memory")
#define CP_WAIT1()  asm volatile("cp.async.wait_group 1;" ::: "memory")
#define CP_WAIT0()  asm volatile("cp.async.wait_group 0;" ::: "memory")

__device__ __forceinline__ void mma16816(float* c, const uint32_t* a, const uint32_t* b) {
    asm("mma.sync.aligned.m16n8k16.row.col.f32.bf16.bf16.f32 "
        "{%0,%1,%2,%3}, {%4,%5,%6,%7}, {%8,%9}, {%0,%1,%2,%3};"
        : "+f"(c[0]), "+f"(c[1]), "+f"(c[2]), "+f"(c[3])
        : "r"(a[0]), "r"(a[1]), "r"(a[2]), "r"(a[3]), "r"(b[0]), "r"(b[1]));
}

__device__ __forceinline__ void ldsm4(uint32_t& r0, uint32_t& r1,
                                      uint32_t& r2, uint32_t& r3, uint32_t a) {
    asm volatile("ldmatrix.sync.aligned.m8n8.x4.shared.b16 {%0,%1,%2,%3}, [%4];"
                 : "=r"(r0), "=r"(r1), "=r"(r2), "=r"(r3) : "r"(a));
}

__device__ __forceinline__ uint32_t pack_bf(__nv_bfloat16 a, __nv_bfloat16 b) {
    __nv_bfloat162 t(a, b);
    return *reinterpret_cast<uint32_t*>(&t);
}

__device__ __forceinline__ void split2(float v0, float v1, uint32_t& hi, uint32_t& lo) {
    __nv_bfloat16 h0 = __float2bfloat16_rn(v0);
    __nv_bfloat16 h1 = __float2bfloat16_rn(v1);
    float r0 = v0 - __bfloat162float(h0);
    float r1 = v1 - __bfloat162float(h1);
    hi = pack_bf(h0, h1);
    lo = pack_bf(__float2bfloat16_rn(r0), __float2bfloat16_rn(r1));
}

// ======================================================================
// conversions
// ======================================================================
__global__ void conv_split(const float* __restrict__ in,
                           __nv_bfloat16* __restrict__ oh,
                           __nv_bfloat16* __restrict__ ol, int n)
{
    int i = blockIdx.x * blockDim.x + threadIdx.x;
    if (i >= n) return;
    float v = in[i];
    __nv_bfloat16 h = __float2bfloat16_rn(v);
    float r = v - __bfloat162float(h);
    oh[i] = h;
    ol[i] = __float2bfloat16_rn(r);
}

__global__ void conv_split_tr(const float* __restrict__ in,
                              __nv_bfloat16* __restrict__ oh,
                              __nv_bfloat16* __restrict__ ol, int K, int N)
{
    int i = blockIdx.x * blockDim.x + threadIdx.x;
    if (i >= K * N) return;
    int k = i / N, n = i % N;
    float v = in[i];
    __nv_bfloat16 h = __float2bfloat16_rn(v);
    float r = v - __bfloat162float(h);
    oh[(size_t)n * K + k] = h;
    ol[(size_t)n * K + k] = __float2bfloat16_rn(r);
}

// ======================================================================
// HMMA GEMM (unchanged from round 12 passing version)
// ======================================================================
#define LDKB 144
#define ATILE (128 * LDKB)
#define BTILE (256 * LDKB)
#define BUFSZ (2 * ATILE + 2 * BTILE)
#define AOFF(buf, v) ((buf) * BUFSZ + (v) * ATILE)
#define BOFF(buf, v) ((buf) * BUFSZ + 2 * ATILE + (v) * BTILE)
#define SMEM_GT (2 * BUFSZ)

__global__ void __launch_bounds__(256, 1) gemm_tc_mma(
    const __nv_bfloat16* __restrict__ Ah, const __nv_bfloat16* __restrict__ Al,
    const __nv_bfloat16* __restrict__ Bh, const __nv_bfloat16* __restrict__ Bl,
    const float* __restrict__ bias, float* __restrict__ Cout,
    int M, int N, int K, int mode)
{
    extern __shared__ char smc[];
    const uint32_t sbase = smem_u32(smc);
    const int tid  = threadIdx.x;
    const int lane = tid & 31;
    const int wid  = tid >> 5;
    const int wm   = wid & 1;
    const int wn   = wid >> 1;
    const int bm = blockIdx.y * 128;
    const int bn = blockIdx.x * 256;

    const char* gA[2] = { (const char*)(Ah + (size_t)bm * K),
                          (const char*)(Al + (size_t)bm * K) };
    const char* gB[2] = { (const char*)(Bh + (size_t)bn * K),
                          (const char*)(Bl + (size_t)bn * K) };

    const int nk = K / 64;

    auto issue_chunk = [&](int k0, int buf) {
#pragma unroll
        for (int v = 0; v < 2; v++) {
#pragma unroll
            for (int j = 0; j < 4; j++) {
                const int idx = j * 256 + tid;
                const int row = idx >> 3, c16 = idx & 7;
                cp16(sbase + AOFF(buf, v) + row * LDKB + c16 * 16,
                     gA[v] + (size_t)row * (K * 2) + k0 * 2 + c16 * 16);
            }
#pragma unroll
            for (int j = 0; j < 8; j++) {
                const int idx = j * 256 + tid;
                const int row = idx >> 3, c16 = idx & 7;
                cp16(sbase + BOFF(buf, v) + row * LDKB + c16 * 16,
                     gB[v] + (size_t)row * (K * 2) + k0 * 2 + c16 * 16);
            }
        }
    };

    issue_chunk(0, 0); CP_COMMIT();
    if (nk > 1) { issue_chunk(64, 1); }
    CP_COMMIT();

    float acc[4][8][4];
#pragma unroll
    for (int i = 0; i < 4; i++)
#pragma unroll
        for (int j = 0; j < 8; j++)
#pragma unroll
            for (int q = 0; q < 4; q++) acc[i][j][q] = 0.f;

    const int lr = lane >> 2;
    const int lc = (lane & 3) * 2;

    const uint32_t aLane = (((lane >> 3) & 1) * 8 + (lane & 7)) * LDKB + (lane >> 4) * 16;
    const uint32_t bLane = ((lane >> 4) * 8 + (lane & 7)) * LDKB + ((lane >> 3) & 1) * 16;

    for (int it = 0; it < nk; ++it) {
        const int buf = it & 1;
        CP_WAIT1();
        __syncthreads();

        const uint32_t sA[2] = { sbase + AOFF(buf, 0), sbase + AOFF(buf, 1) };
        const uint32_t sB[2] = { sbase + BOFF(buf, 0), sbase + BOFF(buf, 1) };

#pragma unroll
        for (int kk = 0; kk < 4; kk++) {
            uint32_t af[2][4][4];
#pragma unroll
            for (int v = 0; v < 2; v++)
#pragma unroll
                for (int i = 0; i < 4; i++)
                    ldsm4(af[v][i][0], af[v][i][1], af[v][i][2], af[v][i][3],
                          sA[v] + (wm * 64 + i * 16) * LDKB + aLane + kk * 32);
            uint32_t bf[2][8][2];
#pragma unroll
            for (int v = 0; v < 2; v++)
#pragma unroll
                for (int jp = 0; jp < 4; jp++)
                    ldsm4(bf[v][2 * jp][0], bf[v][2 * jp][1],
                          bf[v][2 * jp + 1][0], bf[v][2 * jp + 1][1],
                          sB[v] + (wn * 64 + jp * 16) * LDKB + bLane + kk * 32);
#pragma unroll
            for (int i = 0; i < 4; i++)
#pragma unroll
                for (int j = 0; j < 8; j++)
                    mma16816(acc[i][j], af[0][i], bf[0][j]);
#pragma unroll
            for (int i = 0; i < 4; i++)
#pragma unroll
                for (int j = 0; j < 8; j++)
                    mma16816(acc[i][j], af[0][i], bf[1][j]);
#pragma unroll
            for (int i = 0; i < 4; i++)
#pragma unroll
                for (int j = 0; j < 8; j++)
                    mma16816(acc[i][j], af[1][i], bf[0][j]);
        }
        __syncthreads();
        if (it + 2 < nk) { issue_chunk((it + 2) * 64, buf); }
        CP_COMMIT();
    }

    // -------- epilogue --------
#pragma unroll
    for (int i = 0; i < 4; i++) {
        const int row0 = bm + wm * 64 + i * 16 + lr;
#pragma unroll
        for (int j = 0; j < 8; j++) {
            const int col = bn + wn * 64 + j * 8 + lc;
            const float b0 = bias[col], b1 = bias[col + 1];
            const float v00 = acc[i][j][0] + b0, v01 = acc[i][j][1] + b1;
            const float v10 = acc[i][j][2] + b0, v11 = acc[i][j][3] + b1;
            if (mode == 1) {
                *(float2*)&Cout[(size_t)row0 * N + col]       = make_float2(v00, v01);
                *(float2*)&Cout[(size_t)(row0 + 8) * N + col] = make_float2(v10, v11);
            } else {
                const int sel = col / D_;
                const int rem = col % D_;
                const int h   = rem / HD_;
                const int d0  = rem % HD_;
                const int bb0 = row0 >> 12, t0 = row0 & (T_ - 1);
                const int bb1 = (row0 + 8) >> 12, t1 = (row0 + 8) & (T_ - 1);
                if (sel == 2) {
                    const size_t hb0 = (size_t)(bb0 * H_ + h) * HD_;
                    const size_t hb1 = (size_t)(bb1 * H_ + h) * HD_;
                    __nv_bfloat16 h00 = __float2bfloat16_rn(v00);
                    __nv_bfloat16 h01 = __float2bfloat16_rn(v01);
                    __nv_bfloat16 h10 = __float2bfloat16_rn(v10);
                    __nv_bfloat16 h11 = __float2bfloat16_rn(v11);
                    g_vh[(hb0 + d0)     * T_ + t0] = h00;
                    g_vh[(hb0 + d0 + 1) * T_ + t0] = h01;
                    g_vh[(hb1 + d0)     * T_ + t1] = h10;
                    g_vh[(hb1 + d0 + 1) * T_ + t1] = h11;
                    g_vl[(hb0 + d0)     * T_ + t0] = __float2bfloat16_rn(v00 - __bfloat162float(h00));
                    g_vl[(hb0 + d0 + 1) * T_ + t0] = __float2bfloat16_rn(v01 - __bfloat162float(h01));
                    g_vl[(hb1 + d0)     * T_ + t1] = __float2bfloat16_rn(v10 - __bfloat162float(h10));
                    g_vl[(hb1 + d0 + 1) * T_ + t1] = __float2bfloat16_rn(v11 - __bfloat162float(h11));
                } else {
                    __nv_bfloat16* dh = (sel == 0) ? g_qh : g_kh;
                    __nv_bfloat16* dl = (sel == 0) ? g_ql : g_kl;
                    uint32_t hi, lo;
                    split2(v00, v01, hi, lo);
                    size_t off = ((size_t)(bb0 * H_ + h) * T_ + t0) * HD_ + d0;
                    *(uint32_t*)&dh[off] = hi; *(uint32_t*)&dl[off] = lo;
                    split2(v10, v11, hi, lo);
                    off = ((size_t)(bb1 * H_ + h) * T_ + t1) * HD_ + d0;
                    *(uint32_t*)&dh[off] = hi; *(uint32_t*)&dl[off] = lo;
                }
            }
        }
    }
    CP_WAIT0();
}

// ======================================================================
// Causal flash attention, tile-level software pipeline:
// iter kt: [o*=corr_kt; P_kt=split(s); S_{kt+1} MMAs; PV_kt MMAs;
//           softmaxA_{kt+1}] -> softmax overlaps in-flight PV MMAs.
// 4-slot cp.async ring (tiles kt and kt+1 readable simultaneously).
// ======================================================================
#define APB 144
#define AT_KV  (2 * 128 * APB)           // 36864 (Q hi/lo)
#define KVBUF  (4 * 64 * APB)            // 36864 per ring slot
#define SMEM_AT (AT_KV + 4 * KVBUF)      // 184320

__global__ void __launch_bounds__(256, 1) attn_mma()
{
    extern __shared__ char sm[];
    const uint32_t sbase = smem_u32(sm);
    char* sQh = sm;
    char* sQl = sm + 128 * APB;

    const int tid = threadIdx.x, lane = tid & 31, wid = tid >> 5;
    const int lr = lane >> 2, lq = lane & 3;
    const int qi = (int)gridDim.x - 1 - (int)blockIdx.x;
    const int h = blockIdx.y, b = blockIdx.z;
    const int qbase = qi * QT;

    const size_t bh = (size_t)(b * H_ + h) * T_;
    const char* qh = (const char*)(g_qh + (bh + qbase) * HD_);
    const char* ql = (const char*)(g_ql + (bh + qbase) * HD_);
    const char* kh = (const char*)(g_kh + bh * HD_);
    const char* kl = (const char*)(g_kl + bh * HD_);
    const char* vh = (const char*)(g_vh + bh * HD_);   // [hd][T]
    const char* vl = (const char*)(g_vl + bh * HD_);

    auto stage = [&](int kb, int buf) {
        const uint32_t base = sbase + AT_KV + buf * KVBUF;
#pragma unroll
        for (int t = 0; t < 4; t++) {
            const char* src = (t == 0) ? kh : (t == 1) ? kl : (t == 2) ? vh : vl;
#pragma unroll
            for (int j = 0; j < 2; j++) {
                const int idx = j * 256 + tid;
                const int row = idx >> 3, c16 = idx & 7;
                const char* g = (t < 2)
                    ? src + (size_t)(kb + row) * 128 + c16 * 16
                    : src + (size_t)row * (T_ * 2) + (size_t)kb * 2 + c16 * 16;
                cp16(base + t * (64 * APB) + row * APB + c16 * 16, g);
            }
        }
    };

    const int nkt = qbase / KT + 2;   // >= 2

    stage(0, 0); CP_COMMIT();
    stage(KT, 1); CP_COMMIT();
    if (2 < nkt) stage(2 * KT, 2);
    CP_COMMIT();

    // stage Q (plain loads, overlap with cp.async)
#pragma unroll
    for (int p = 0; p < 4; p++) {
        const int idx = p * 256 + tid;
        const int row = idx >> 3, c16 = idx & 7;
        *(uint4*)(sQh + row * APB + c16 * 16) =
            *(const uint4*)(qh + (size_t)row * 128 + c16 * 16);
        *(uint4*)(sQl + row * APB + c16 * 16) =
            *(const uint4*)(ql + (size_t)row * 128 + c16 * 16);
    }
    CP_WAIT2();          // tile 0 resident
    __syncthreads();

    // hoist Q fragments
    uint32_t qf[4][2][4];
    {
        const int r0 = (wid * 16 + lr) * APB;
#pragma unroll
        for (int kk = 0; kk < 4; kk++) {
            const int kbo = kk * 32 + lq * 4;
            qf[kk][0][0] = *(const uint32_t*)(sQh + r0 + kbo);
            qf[kk][0][1] = *(const uint32_t*)(sQh + r0 + 8 * APB + kbo);
            qf[kk][0][2] = *(const uint32_t*)(sQh + r0 + kbo + 16);
            qf[kk][0][3] = *(const uint32_t*)(sQh + r0 + 8 * APB + kbo + 16);
            qf[kk][1][0] = *(const uint32_t*)(sQl + r0 + kbo);
            qf[kk][1][1] = *(const uint32_t*)(sQl + r0 + 8 * APB + kbo);
            qf[kk][1][2] = *(const uint32_t*)(sQl + r0 + kbo + 16);
            qf[kk][1][3] = *(const uint32_t*)(sQl + r0 + 8 * APB + kbo + 16);
        }
    }

    float m[2] = {-1e30f, -1e30f}, l[2] = {0.f, 0.f}, cr[2] = {0.f, 0.f};
    float o[8][4];
#pragma unroll
    for (int j = 0; j < 8; j++)
#pragma unroll
        for (int q = 0; q < 4; q++) o[j][q] = 0.f;
    float s[8][4];

    const int rowmaxw = qbase + wid * 16 + 15;
    const uint32_t kvLane = ((lane >> 4) * 8 + (lane & 7)) * APB + ((lane >> 3) & 1) * 16;

    uint32_t bfh[2][8][2], bfl[2][8][2];

    // ---- S MMAs for a tile into s (reads K at slot base) ----
    auto computeS = [&](uint32_t slotBase) {
        const uint32_t kB = slotBase, klB = slotBase + 64 * APB;
#pragma unroll
        for (int j = 0; j < 8; j++)
#pragma unroll
            for (int q = 0; q < 4; q++) s[j][q] = 0.f;
        auto loadK = [&](int kk, int pb) {
#pragma unroll
            for (int jp = 0; jp < 4; jp++) {
                ldsm4(bfh[pb][2 * jp][0], bfh[pb][2 * jp][1],
                      bfh[pb][2 * jp + 1][0], bfh[pb][2 * jp + 1][1],
                      kB + jp * 16 * APB + kvLane + kk * 32);
                ldsm4(bfl[pb][2 * jp][0], bfl[pb][2 * jp][1],
                      bfl[pb][2 * jp + 1][0], bfl[pb][2 * jp + 1][1],
                      klB + jp * 16 * APB + kvLane + kk * 32);
            }
        };
        loadK(0, 0);
#pragma unroll
        for (int kk = 0; kk < 4; kk++) {
            const int pb = kk & 1;
            if (kk < 3) loadK(kk + 1, pb ^ 1);
#pragma unroll
            for (int j = 0; j < 8; j++) mma16816(s[j], qf[kk][0], bfh[pb][j]);
#pragma unroll
            for (int j = 0; j < 8; j++) mma16816(s[j], qf[kk][0], bfl[pb][j]);
#pragma unroll
            for (int j = 0; j < 8; j++) mma16816(s[j], qf[kk][1], bfh[pb][j]);
        }
    };

    // ---- softmaxA: mask/scale + max/exp/sum; updates m, l, cr (NOT o) ----
    auto softmaxA = [&](int kb) {
        const bool needmask = (kb + 63) > (qbase + wid * 16);
        if (needmask) {
            const int row_a = qbase + wid * 16 + lr;
#pragma unroll
            for (int j = 0; j < 8; j++) {
                const int col0 = kb + j * 8 + lq * 2;
                s[j][0] = (col0     <= row_a)     ? s[j][0] * SCALE_ : -1e30f;
                s[j][1] = (col0 + 1 <= row_a)     ? s[j][1] * SCALE_ : -1e30f;
                s[j][2] = (col0     <= row_a + 8) ? s[j][2] * SCALE_ : -1e30f;
                s[j][3] = (col0 + 1 <= row_a + 8) ? s[j][3] * SCALE_ : -1e30f;
            }
        } else {
#pragma unroll
            for (int j = 0; j < 8; j++)
#pragma unroll
                for (int q = 0; q < 4; q++) s[j][q] *= SCALE_;
        }
#pragma unroll
        for (int r = 0; r < 2; r++) {
            float mx = -1e30f;
#pragma unroll
            for (int j = 0; j < 8; j++)
                mx = fmaxf(mx, fmaxf(s[j][2 * r], s[j][2 * r + 1]));
            mx = fmaxf(mx, __shfl_xor_sync(0xffffffffu, mx, 1));
            mx = fmaxf(mx, __shfl_xor_sync(0xffffffffu, mx, 2));
            const float mnew = fmaxf(m[r], mx);
            cr[r] = __expf(m[r] - mnew);
            float sum = 0.f;
#pragma unroll
            for (int j = 0; j < 8; j++) {
                const float p0 = __expf(s[j][2 * r]     - mnew);
                const float p1 = __expf(s[j][2 * r + 1] - mnew);
                s[j][2 * r] = p0; s[j][2 * r + 1] = p1;
                sum += p0 + p1;
            }
            sum += __shfl_xor_sync(0xffffffffu, sum, 1);
            sum += __shfl_xor_sync(0xffffffffu, sum, 2);
            l[r] = l[r] * cr[r] + sum;
            m[r] = mnew;
        }
    };

    // prologue: S_0 + softmaxA_0 (tile 0 is active for every warp)
    computeS(sbase + AT_KV + 0 * KVBUF);
    softmaxA(0);

    for (int kt = 0; kt < nkt; kt++) {
        CP_WAIT1();          // tiles <= kt+1 resident
        __syncthreads();     // all warps done with slot (kt+3)&3 (read in iter kt-1)
        if (kt + 3 < nkt) stage((kt + 3) * KT, (kt + 3) & 3);
        CP_COMMIT();

        const bool act  = (kt * KT <= rowmaxw);
        const int  kn   = kt + 1;
        const bool actn = (kn < nkt) && (kn * KT <= rowmaxw);

        uint32_t ph0[8], ph1[8], pl0[8], pl1[8];
        if (act) {
            // apply deferred correction, then split s_kt -> P fragments
#pragma unroll
            for (int r = 0; r < 2; r++)
#pragma unroll
                for (int j = 0; j < 8; j++) {
                    o[j][2 * r] *= cr[r]; o[j][2 * r + 1] *= cr[r];
                }
#pragma unroll
            for (int j = 0; j < 8; j++) {
                split2(s[j][0], s[j][1], ph0[j], pl0[j]);
                split2(s[j][2], s[j][3], ph1[j], pl1[j]);
            }
        }

        // S MMAs for NEXT tile (s freed by the split above)
        if (actn)
            computeS(sbase + AT_KV + (kn & 3) * KVBUF);

        // PV MMAs for THIS tile (independent of softmax of next tile)
        if (act) {
            const uint32_t vB  = sbase + AT_KV + (kt & 3) * KVBUF + 2 * 64 * APB;
            const uint32_t vlB = vB + 64 * APB;
            auto loadV = [&](int kk, int pb) {
#pragma unroll
                for (int jp = 0; jp < 4; jp++) {
                    ldsm4(bfh[pb][2 * jp][0], bfh[pb][2 * jp][1],
                          bfh[pb][2 * jp + 1][0], bfh[pb][2 * jp + 1][1],
                          vB + jp * 16 * APB + kvLane + kk * 32);
                    ldsm4(bfl[pb][2 * jp][0], bfl[pb][2 * jp][1],
                          bfl[pb][2 * jp + 1][0], bfl[pb][2 * jp + 1][1],
                          vlB + jp * 16 * APB + kvLane + kk * 32);
                }
            };
            loadV(0, 0);
#pragma unroll
            for (int kk = 0; kk < 4; kk++) {
                const int pb = kk & 1;
                if (kk < 3) loadV(kk + 1, pb ^ 1);
                uint32_t a_h[4] = { ph0[2 * kk], ph1[2 * kk], ph0[2 * kk + 1], ph1[2 * kk + 1] };
                uint32_t a_l[4] = { pl0[2 * kk], pl1[2 * kk], pl0[2 * kk + 1], pl1[2 * kk + 1] };
#pragma unroll
                for (int jn = 0; jn < 8; jn++) mma16816(o[jn], a_h, bfh[pb][jn]);
#pragma unroll
                for (int jn = 0; jn < 8; jn++) mma16816(o[jn], a_h, bfl[pb][jn]);
#pragma unroll
                for (int jn = 0; jn < 8; jn++) mma16816(o[jn], a_l, bfh[pb][jn]);
            }
        }

        // softmax of NEXT tile overlaps in-flight PV MMAs
        if (actn)
            softmaxA(kn * KT);
    }

    // ---- epilogue ----
    const float inv0 = 1.f / l[0], inv1 = 1.f / l[1];
    const int t0 = qbase + wid * 16 + lr;
    const int t1 = t0 + 8;
#pragma unroll
    for (int jn = 0; jn < 8; jn++) {
        const int d = h * HD_ + jn * 8 + lq * 2;
        uint32_t hi, lo;
        split2(o[jn][0] * inv0, o[jn][1] * inv0, hi, lo);
        size_t off = (size_t)(b * T_ + t0) * D_ + d;
        *(uint32_t*)&g_ah[off] = hi; *(uint32_t*)&g_al[off] = lo;
        split2(o[jn][2] * inv1, o[jn][3] * inv1, hi, lo);
        off = (size_t)(b * T_ + t1) * D_ + d;
        *(uint32_t*)&g_ah[off] = hi; *(uint32_t*)&g_al[off] = lo;
    }
    CP_WAIT0();
}

// ======================================================================
extern "C" void kernel_launch(void* const* d_in, const int* in_sizes, int n_in,
                              void* d_out, int out_size)
{
    const float* x      = (const float*)d_in[0];
    const float* W_qkv  = (const float*)d_in[1];
    const float* b_qkv  = (const float*)d_in[2];
    const float* W_out  = (const float*)d_in[3];
    const float* b_out  = (const float*)d_in[4];
    float* out = (float*)d_out;

    __nv_bfloat16 *xh, *xl, *ah, *al, *wqh, *wql, *woh, *wol;
    cudaGetSymbolAddress((void**)&xh,  g_xh);
    cudaGetSymbolAddress((void**)&xl,  g_xl);
    cudaGetSymbolAddress((void**)&ah,  g_ah);
    cudaGetSymbolAddress((void**)&al,  g_al);
    cudaGetSymbolAddress((void**)&wqh, g_wqh);
    cudaGetSymbolAddress((void**)&wql, g_wql);
    cudaGetSymbolAddress((void**)&woh, g_woh);
    cudaGetSymbolAddress((void**)&wol, g_wol);

    cudaFuncSetAttribute(gemm_tc_mma, cudaFuncAttributeMaxDynamicSharedMemorySize, SMEM_GT);
    cudaFuncSetAttribute(attn_mma,    cudaFuncAttributeMaxDynamicSharedMemorySize, SMEM_AT);

    const int nX = B_ * T_ * D_;

    conv_split<<<(nX + 255) / 256, 256>>>(x, xh, xl, nX);
    conv_split_tr<<<(D_ * 3 * D_ + 255) / 256, 256>>>(W_qkv, wqh, wql, D_, 3 * D_);
    conv_split_tr<<<(D_ * D_ + 255) / 256, 256>>>(W_out, woh, wol, D_, D_);

    {
        dim3 grid((3 * D_) / 256, (B_ * T_) / 128);
        gemm_tc_mma<<<grid, 256, SMEM_GT>>>(xh, xl, wqh, wql, b_qkv, nullptr,
                                            B_ * T_, 3 * D_, D_, 0);
    }
    {
        dim3 grid(T_ / QT, H_, B_);
        attn_mma<<<grid, 256, SMEM_AT>>>();
    }
    {
        dim3 grid(D_ / 256, (B_ * T_) / 128);
        gemm_tc_mma<<<grid, 256, SMEM_GT>>>(ah, al, woh, wol, b_out, out,
                                            B_ * T_, D_, D_, 1);
    }
}

// round 14
// speedup vs baseline: 1.0926x; 1.0926x over previous
#include <cuda_runtime.h>
#include <cuda_bf16.h>
#include <cstdint>

#define B_   2
#define T_   4096
#define D_   768
#define H_   12
#define HD_  64
#define SCALE_ 0.125f

#define QT 128

// ---------------- scratch ----------------
__device__ __nv_bfloat16 g_qh[(size_t)B_ * H_ * T_ * HD_];   // [B,H,T,hd]
__device__ __nv_bfloat16 g_ql[(size_t)B_ * H_ * T_ * HD_];
__device__ __nv_bfloat16 g_kh[(size_t)B_ * H_ * T_ * HD_];
__device__ __nv_bfloat16 g_kl[(size_t)B_ * H_ * T_ * HD_];
__device__ __nv_bfloat16 g_vh[(size_t)B_ * H_ * T_ * HD_];   // TRANSPOSED: [B,H,hd,T]
__device__ __nv_bfloat16 g_vl[(size_t)B_ * H_ * T_ * HD_];
__device__ __nv_bfloat16 g_xh[(size_t)B_ * T_ * D_];
__device__ __nv_bfloat16 g_xl[(size_t)B_ * T_ * D_];
__device__ __nv_bfloat16 g_ah[(size_t)B_ * T_ * D_];
__device__ __nv_bfloat16 g_al[(size_t)B_ * T_ * D_];
__device__ __nv_bfloat16 g_wqh[(size_t)3 * D_ * D_];
__device__ __nv_bfloat16 g_wql[(size_t)3 * D_ * D_];
__device__ __nv_bfloat16 g_woh[(size_t)D_ * D_];
__device__ __nv_bfloat16 g_wol[(size_t)D_ * D_];

// ======================= helpers ========================
__device__ __forceinline__ uint32_t smem_u32(const void* p) {
    uint32_t a;
    asm("{ .reg .u64 t; cvta.to.shared.u64 t, %1; cvt.u32.u64 %0, t; }"
        : "=r"(a) : "l"(p));
    return a;
}

__device__ __forceinline__ void cp16(uint32_t s, const void* g) {
    asm volatile("cp.async.cg.shared.global [%0], [%1], 16;" :: "r"(s), "l"(g));
}
#define CP_COMMIT() asm volatile("cp.async.commit_group;" ::: "memory")
#define CP_WAIT1()  asm volatile("cp.async.wait_group 1;" ::: "memory")
#define CP_WAIT0()  asm volatile("cp.async.wait_group 0;" ::: "memory")

__device__ __forceinline__ void mma16816(float* c, const uint32_t* a, const uint32_t* b) {
    asm("mma.sync.aligned.m16n8k16.row.col.f32.bf16.bf16.f32 "
        "{%0,%1,%2,%3}, {%4,%5,%6,%7}, {%8,%9}, {%0,%1,%2,%3};"
        : "+f"(c[0]), "+f"(c[1]), "+f"(c[2]), "+f"(c[3])
        : "r"(a[0]), "r"(a[1]), "r"(a[2]), "r"(a[3]), "r"(b[0]), "r"(b[1]));
}

__device__ __forceinline__ void ldsm4(uint32_t& r0, uint32_t& r1,
                                      uint32_t& r2, uint32_t& r3, uint32_t a) {
    asm volatile("ldmatrix.sync.aligned.m8n8.x4.shared.b16 {%0,%1,%2,%3}, [%4];"
                 : "=r"(r0), "=r"(r1), "=r"(r2), "=r"(r3) : "r"(a));
}

__device__ __forceinline__ uint32_t pack_bf(__nv_bfloat16 a, __nv_bfloat16 b) {
    __nv_bfloat162 t(a, b);
    return *reinterpret_cast<uint32_t*>(&t);
}

__device__ __forceinline__ void split2(float v0, float v1, uint32_t& hi, uint32_t& lo) {
    __nv_bfloat16 h0 = __float2bfloat16_rn(v0);
    __nv_bfloat16 h1 = __float2bfloat16_rn(v1);
    float r0 = v0 - __bfloat162float(h0);
    float r1 = v1 - __bfloat162float(h1);
    hi = pack_bf(h0, h1);
    lo = pack_bf(__float2bfloat16_rn(r0), __float2bfloat16_rn(r1));
}

// ======================================================================
// conversions
// ======================================================================
__global__ void conv_split(const float* __restrict__ in,
                           __nv_bfloat16* __restrict__ oh,
                           __nv_bfloat16* __restrict__ ol, int n)
{
    int i = blockIdx.x * blockDim.x + threadIdx.x;
    if (i >= n) return;
    float v = in[i];
    __nv_bfloat16 h = __float2bfloat16_rn(v);
    float r = v - __bfloat162float(h);
    oh[i] = h;
    ol[i] = __float2bfloat16_rn(r);
}

// coalesced tiled transpose-split: in[K][N] fp32 -> oh/ol[N][K] bf16
__global__ void conv_split_tr(const float* __restrict__ in,
                              __nv_bfloat16* __restrict__ oh,
                              __nv_bfloat16* __restrict__ ol, int K, int N)
{
    __shared__ float t[32][33];
    const int bn = blockIdx.x * 32;   // n base
    const int bk = blockIdx.y * 32;   // k base
    const int tx = threadIdx.x;       // 0..31
    const int ty = threadIdx.y;       // 0..7
#pragma unroll
    for (int p = 0; p < 4; p++)
        t[ty + p * 8][tx] = in[(size_t)(bk + ty + p * 8) * N + bn + tx];
    __syncthreads();
#pragma unroll
    for (int p = 0; p < 4; p++) {
        const float v = t[tx][ty + p * 8];
        __nv_bfloat16 h = __float2bfloat16_rn(v);
        const size_t off = (size_t)(bn + ty + p * 8) * K + bk + tx;
        oh[off] = h;
        ol[off] = __float2bfloat16_rn(v - __bfloat162float(h));
    }
}

// ======================================================================
// HMMA GEMM (unchanged from round 12 passing version)
// ======================================================================
#define LDKB 144
#define ATILE (128 * LDKB)
#define BTILE (256 * LDKB)
#define BUFSZ (2 * ATILE + 2 * BTILE)
#define AOFF(buf, v) ((buf) * BUFSZ + (v) * ATILE)
#define BOFF(buf, v) ((buf) * BUFSZ + 2 * ATILE + (v) * BTILE)
#define SMEM_GT (2 * BUFSZ)

__global__ void __launch_bounds__(256, 1) gemm_tc_mma(
    const __nv_bfloat16* __restrict__ Ah, const __nv_bfloat16* __restrict__ Al,
    const __nv_bfloat16* __restrict__ Bh, const __nv_bfloat16* __restrict__ Bl,
    const float* __restrict__ bias, float* __restrict__ Cout,
    int M, int N, int K, int mode)
{
    extern __shared__ char smc[];
    const uint32_t sbase = smem_u32(smc);
    const int tid  = threadIdx.x;
    const int lane = tid & 31;
    const int wid  = tid >> 5;
    const int wm   = wid & 1;
    const int wn   = wid >> 1;
    const int bm = blockIdx.y * 128;
    const int bn = blockIdx.x * 256;

    const char* gA[2] = { (const char*)(Ah + (size_t)bm * K),
                          (const char*)(Al + (size_t)bm * K) };
    const char* gB[2] = { (const char*)(Bh + (size_t)bn * K),
                          (const char*)(Bl + (size_t)bn * K) };

    const int nk = K / 64;

    auto issue_chunk = [&](int k0, int buf) {
#pragma unroll
        for (int v = 0; v < 2; v++) {
#pragma unroll
            for (int j = 0; j < 4; j++) {
                const int idx = j * 256 + tid;
                const int row = idx >> 3, c16 = idx & 7;
                cp16(sbase + AOFF(buf, v) + row * LDKB + c16 * 16,
                     gA[v] + (size_t)row * (K * 2) + k0 * 2 + c16 * 16);
            }
#pragma unroll
            for (int j = 0; j < 8; j++) {
                const int idx = j * 256 + tid;
                const int row = idx >> 3, c16 = idx & 7;
                cp16(sbase + BOFF(buf, v) + row * LDKB + c16 * 16,
                     gB[v] + (size_t)row * (K * 2) + k0 * 2 + c16 * 16);
            }
        }
    };

    issue_chunk(0, 0); CP_COMMIT();
    if (nk > 1) { issue_chunk(64, 1); }
    CP_COMMIT();

    float acc[4][8][4];
#pragma unroll
    for (int i = 0; i < 4; i++)
#pragma unroll
        for (int j = 0; j < 8; j++)
#pragma unroll
            for (int q = 0; q < 4; q++) acc[i][j][q] = 0.f;

    const int lr = lane >> 2;
    const int lc = (lane & 3) * 2;

    const uint32_t aLane = (((lane >> 3) & 1) * 8 + (lane & 7)) * LDKB + (lane >> 4) * 16;
    const uint32_t bLane = ((lane >> 4) * 8 + (lane & 7)) * LDKB + ((lane >> 3) & 1) * 16;

    for (int it = 0; it < nk; ++it) {
        const int buf = it & 1;
        CP_WAIT1();
        __syncthreads();

        const uint32_t sA[2] = { sbase + AOFF(buf, 0), sbase + AOFF(buf, 1) };
        const uint32_t sB[2] = { sbase + BOFF(buf, 0), sbase + BOFF(buf, 1) };

#pragma unroll
        for (int kk = 0; kk < 4; kk++) {
            uint32_t af[2][4][4];
#pragma unroll
            for (int v = 0; v < 2; v++)
#pragma unroll
                for (int i = 0; i < 4; i++)
                    ldsm4(af[v][i][0], af[v][i][1], af[v][i][2], af[v][i][3],
                          sA[v] + (wm * 64 + i * 16) * LDKB + aLane + kk * 32);
            uint32_t bf[2][8][2];
#pragma unroll
            for (int v = 0; v < 2; v++)
#pragma unroll
                for (int jp = 0; jp < 4; jp++)
                    ldsm4(bf[v][2 * jp][0], bf[v][2 * jp][1],
                          bf[v][2 * jp + 1][0], bf[v][2 * jp + 1][1],
                          sB[v] + (wn * 64 + jp * 16) * LDKB + bLane + kk * 32);
#pragma unroll
            for (int i = 0; i < 4; i++)
#pragma unroll
                for (int j = 0; j < 8; j++)
                    mma16816(acc[i][j], af[0][i], bf[0][j]);
#pragma unroll
            for (int i = 0; i < 4; i++)
#pragma unroll
                for (int j = 0; j < 8; j++)
                    mma16816(acc[i][j], af[0][i], bf[1][j]);
#pragma unroll
            for (int i = 0; i < 4; i++)
#pragma unroll
                for (int j = 0; j < 8; j++)
                    mma16816(acc[i][j], af[1][i], bf[0][j]);
        }
        __syncthreads();
        if (it + 2 < nk) { issue_chunk((it + 2) * 64, buf); }
        CP_COMMIT();
    }

    // -------- epilogue --------
#pragma unroll
    for (int i = 0; i < 4; i++) {
        const int row0 = bm + wm * 64 + i * 16 + lr;
#pragma unroll
        for (int j = 0; j < 8; j++) {
            const int col = bn + wn * 64 + j * 8 + lc;
            const float b0 = bias[col], b1 = bias[col + 1];
            const float v00 = acc[i][j][0] + b0, v01 = acc[i][j][1] + b1;
            const float v10 = acc[i][j][2] + b0, v11 = acc[i][j][3] + b1;
            if (mode == 1) {
                *(float2*)&Cout[(size_t)row0 * N + col]       = make_float2(v00, v01);
                *(float2*)&Cout[(size_t)(row0 + 8) * N + col] = make_float2(v10, v11);
            } else {
                const int sel = col / D_;
                const int rem = col % D_;
                const int h   = rem / HD_;
                const int d0  = rem % HD_;
                const int bb0 = row0 >> 12, t0 = row0 & (T_ - 1);
                const int bb1 = (row0 + 8) >> 12, t1 = (row0 + 8) & (T_ - 1);
                if (sel == 2) {
                    const size_t hb0 = (size_t)(bb0 * H_ + h) * HD_;
                    const size_t hb1 = (size_t)(bb1 * H_ + h) * HD_;
                    __nv_bfloat16 h00 = __float2bfloat16_rn(v00);
                    __nv_bfloat16 h01 = __float2bfloat16_rn(v01);
                    __nv_bfloat16 h10 = __float2bfloat16_rn(v10);
                    __nv_bfloat16 h11 = __float2bfloat16_rn(v11);
                    g_vh[(hb0 + d0)     * T_ + t0] = h00;
                    g_vh[(hb0 + d0 + 1) * T_ + t0] = h01;
                    g_vh[(hb1 + d0)     * T_ + t1] = h10;
                    g_vh[(hb1 + d0 + 1) * T_ + t1] = h11;
                    g_vl[(hb0 + d0)     * T_ + t0] = __float2bfloat16_rn(v00 - __bfloat162float(h00));
                    g_vl[(hb0 + d0 + 1) * T_ + t0] = __float2bfloat16_rn(v01 - __bfloat162float(h01));
                    g_vl[(hb1 + d0)     * T_ + t1] = __float2bfloat16_rn(v10 - __bfloat162float(h10));
                    g_vl[(hb1 + d0 + 1) * T_ + t1] = __float2bfloat16_rn(v11 - __bfloat162float(h11));
                } else {
                    __nv_bfloat16* dh = (sel == 0) ? g_qh : g_kh;
                    __nv_bfloat16* dl = (sel == 0) ? g_ql : g_kl;
                    uint32_t hi, lo;
                    split2(v00, v01, hi, lo);
                    size_t off = ((size_t)(bb0 * H_ + h) * T_ + t0) * HD_ + d0;
                    *(uint32_t*)&dh[off] = hi; *(uint32_t*)&dl[off] = lo;
                    split2(v10, v11, hi, lo);
                    off = ((size_t)(bb1 * H_ + h) * T_ + t1) * HD_ + d0;
                    *(uint32_t*)&dh[off] = hi; *(uint32_t*)&dl[off] = lo;
                }
            }
        }
    }
    CP_WAIT0();
}

// ======================================================================
// Causal flash attention (R12 inner math), 128-key SUPER-TILES:
// one __syncthreads + one stage per 128 keys, two 64-key compute passes.
// 2-slot ring: slot = K hi/lo [128 x 144B] + V^T hi/lo [64 x 272B].
// smem: Q 36864 + 2 x 71680 = 180224
// ======================================================================
#define APB 144
#define VPB 272
#define KSZ (128 * APB)                  // 18432 per K buffer
#define VSZ (64 * VPB)                   // 17408 per V buffer
#define SLOT (2 * KSZ + 2 * VSZ)         // 71680
#define AT_KV (2 * 128 * APB)            // 36864 (Q hi/lo)
#define SMEM_AT (AT_KV + 2 * SLOT)       // 180224

__global__ void __launch_bounds__(256, 1) attn_mma()
{
    extern __shared__ char sm[];
    const uint32_t sbase = smem_u32(sm);
    char* sQh = sm;
    char* sQl = sm + 128 * APB;

    const int tid = threadIdx.x, lane = tid & 31, wid = tid >> 5;
    const int lr = lane >> 2, lq = lane & 3;
    const int qi = (int)gridDim.x - 1 - (int)blockIdx.x;
    const int h = blockIdx.y, b = blockIdx.z;
    const int qbase = qi * QT;

    const size_t bh = (size_t)(b * H_ + h) * T_;
    const char* qh = (const char*)(g_qh + (bh + qbase) * HD_);
    const char* ql = (const char*)(g_ql + (bh + qbase) * HD_);
    const char* kh = (const char*)(g_kh + bh * HD_);
    const char* kl = (const char*)(g_kl + bh * HD_);
    const char* vh = (const char*)(g_vh + bh * HD_);   // [hd][T]
    const char* vl = (const char*)(g_vl + bh * HD_);

    // stage one 128-key super-tile into ring slot `buf`
    auto stage = [&](int kb, int buf) {
        const uint32_t base = sbase + AT_KV + buf * SLOT;
        // K hi/lo: 128 rows x 8 c16 each
#pragma unroll
        for (int t = 0; t < 2; t++) {
            const char* src = t ? kl : kh;
#pragma unroll
            for (int j = 0; j < 4; j++) {
                const int idx = j * 256 + tid;        // 0..1023
                const int row = idx >> 3, c16 = idx & 7;
                cp16(base + t * KSZ + row * APB + c16 * 16,
                     src + (size_t)(kb + row) * 128 + c16 * 16);
            }
        }
        // V^T hi/lo: 64 rows x 16 c16 each (256B of keys per row)
#pragma unroll
        for (int t = 0; t < 2; t++) {
            const char* src = t ? vl : vh;
#pragma unroll
            for (int j = 0; j < 4; j++) {
                const int idx = j * 256 + tid;        // 0..1023
                const int row = idx >> 4, c16 = idx & 15;
                cp16(base + 2 * KSZ + t * VSZ + row * VPB + c16 * 16,
                     src + (size_t)row * (T_ * 2) + (size_t)kb * 2 + c16 * 16);
            }
        }
    };

    const int nslot = qi + 1;   // 128-key super-tiles with kb <= qbase+127

    stage(0, 0); CP_COMMIT();

    // stage Q (plain loads overlap the cp.async)
#pragma unroll
    for (int p = 0; p < 4; p++) {
        const int idx = p * 256 + tid;
        const int row = idx >> 3, c16 = idx & 7;
        *(uint4*)(sQh + row * APB + c16 * 16) =
            *(const uint4*)(qh + (size_t)row * 128 + c16 * 16);
        *(uint4*)(sQl + row * APB + c16 * 16) =
            *(const uint4*)(ql + (size_t)row * 128 + c16 * 16);
    }
    __syncthreads();

    // hoist Q fragments
    uint32_t qf[4][2][4];
    {
        const int r0 = (wid * 16 + lr) * APB;
#pragma unroll
        for (int kk = 0; kk < 4; kk++) {
            const int kbo = kk * 32 + lq * 4;
            qf[kk][0][0] = *(const uint32_t*)(sQh + r0 + kbo);
            qf[kk][0][1] = *(const uint32_t*)(sQh + r0 + 8 * APB + kbo);
            qf[kk][0][2] = *(const uint32_t*)(sQh + r0 + kbo + 16);
            qf[kk][0][3] = *(const uint32_t*)(sQh + r0 + 8 * APB + kbo + 16);
            qf[kk][1][0] = *(const uint32_t*)(sQl + r0 + kbo);
            qf[kk][1][1] = *(const uint32_t*)(sQl + r0 + 8 * APB + kbo);
            qf[kk][1][2] = *(const uint32_t*)(sQl + r0 + kbo + 16);
            qf[kk][1][3] = *(const uint32_t*)(sQl + r0 + 8 * APB + kbo + 16);
        }
    }

    float m[2] = {-1e30f, -1e30f}, l[2] = {0.f, 0.f};
    float o[8][4];
#pragma unroll
    for (int j = 0; j < 8; j++)
#pragma unroll
        for (int q = 0; q < 4; q++) o[j][q] = 0.f;

    const int rowmaxw = qbase + wid * 16 + 15;
    const uint32_t kvLane = ((lane >> 4) * 8 + (lane & 7)) * APB + ((lane >> 3) & 1) * 16;
    const uint32_t vLane  = ((lane >> 4) * 8 + (lane & 7)) * VPB + ((lane >> 3) & 1) * 16;

    uint32_t bfh[2][8][2], bfl[2][8][2];

    for (int st = 0; st < nslot; st++) {
        CP_WAIT0();          // slot st resident (this thread's copies; barrier covers rest)
        __syncthreads();     // all threads' copies done; slot (st+1)&1 free
        if (st + 1 < nslot) stage((st + 1) * 128, (st + 1) & 1);
        CP_COMMIT();

        const uint32_t slotB = sbase + AT_KV + (st & 1) * SLOT;

#pragma unroll
        for (int half = 0; half < 2; half++) {
            const int kb = st * 128 + half * 64;
            if (kb > rowmaxw) continue;

            const uint32_t kB  = slotB + half * 64 * APB;
            const uint32_t klB = slotB + KSZ + half * 64 * APB;
            const uint32_t vB  = slotB + 2 * KSZ + half * 128;          // byte offset in key dim
            const uint32_t vlB = slotB + 2 * KSZ + VSZ + half * 128;

            // ---- S = Q K^T (pipelined K frags, ldmatrix) ----
            float s[8][4];
#pragma unroll
            for (int j = 0; j < 8; j++)
#pragma unroll
                for (int q = 0; q < 4; q++) s[j][q] = 0.f;

            auto loadK = [&](int kk, int pb) {
#pragma unroll
                for (int jp = 0; jp < 4; jp++) {
                    ldsm4(bfh[pb][2 * jp][0], bfh[pb][2 * jp][1],
                          bfh[pb][2 * jp + 1][0], bfh[pb][2 * jp + 1][1],
                          kB + jp * 16 * APB + kvLane + kk * 32);
                    ldsm4(bfl[pb][2 * jp][0], bfl[pb][2 * jp][1],
                          bfl[pb][2 * jp + 1][0], bfl[pb][2 * jp + 1][1],
                          klB + jp * 16 * APB + kvLane + kk * 32);
                }
            };

            loadK(0, 0);
#pragma unroll
            for (int kk = 0; kk < 4; kk++) {
                const int pb = kk & 1;
                if (kk < 3) loadK(kk + 1, pb ^ 1);
#pragma unroll
                for (int j = 0; j < 8; j++) mma16816(s[j], qf[kk][0], bfh[pb][j]);
#pragma unroll
                for (int j = 0; j < 8; j++) mma16816(s[j], qf[kk][0], bfl[pb][j]);
#pragma unroll
                for (int j = 0; j < 8; j++) mma16816(s[j], qf[kk][1], bfh[pb][j]);
            }

            // ---- scale + causal mask ----
            const bool needmask = (kb + 63) > (qbase + wid * 16);
            if (needmask) {
                const int row_a = qbase + wid * 16 + lr;
#pragma unroll
                for (int j = 0; j < 8; j++) {
                    const int col0 = kb + j * 8 + lq * 2;
                    s[j][0] = (col0     <= row_a)     ? s[j][0] * SCALE_ : -1e30f;
                    s[j][1] = (col0 + 1 <= row_a)     ? s[j][1] * SCALE_ : -1e30f;
                    s[j][2] = (col0     <= row_a + 8) ? s[j][2] * SCALE_ : -1e30f;
                    s[j][3] = (col0 + 1 <= row_a + 8) ? s[j][3] * SCALE_ : -1e30f;
                }
            } else {
#pragma unroll
                for (int j = 0; j < 8; j++)
#pragma unroll
                    for (int q = 0; q < 4; q++) s[j][q] *= SCALE_;
            }

            // ---- online softmax ----
#pragma unroll
            for (int r = 0; r < 2; r++) {
                float mx = -1e30f;
#pragma unroll
                for (int j = 0; j < 8; j++)
                    mx = fmaxf(mx, fmaxf(s[j][2 * r], s[j][2 * r + 1]));
                mx = fmaxf(mx, __shfl_xor_sync(0xffffffffu, mx, 1));
                mx = fmaxf(mx, __shfl_xor_sync(0xffffffffu, mx, 2));
                const float mnew = fmaxf(m[r], mx);
                const float corr = __expf(m[r] - mnew);
                float sum = 0.f;
#pragma unroll
                for (int j = 0; j < 8; j++) {
                    const float p0 = __expf(s[j][2 * r]     - mnew);
                    const float p1 = __expf(s[j][2 * r + 1] - mnew);
                    s[j][2 * r] = p0; s[j][2 * r + 1] = p1;
                    sum += p0 + p1;
                }
                sum += __shfl_xor_sync(0xffffffffu, sum, 1);
                sum += __shfl_xor_sync(0xffffffffu, sum, 2);
                l[r] = l[r] * corr + sum;
                m[r] = mnew;
#pragma unroll
                for (int j = 0; j < 8; j++) {
                    o[j][2 * r] *= corr; o[j][2 * r + 1] *= corr;
                }
            }

            // ---- P fragments (split) ----
            uint32_t ph0[8], ph1[8], pl0[8], pl1[8];
#pragma unroll
            for (int j = 0; j < 8; j++) {
                split2(s[j][0], s[j][1], ph0[j], pl0[j]);
                split2(s[j][2], s[j][3], ph1[j], pl1[j]);
            }

            // ---- O += P V (pipelined V frags, ldmatrix) ----
            auto loadV = [&](int kk, int pb) {
#pragma unroll
                for (int jp = 0; jp < 4; jp++) {
                    ldsm4(bfh[pb][2 * jp][0], bfh[pb][2 * jp][1],
                          bfh[pb][2 * jp + 1][0], bfh[pb][2 * jp + 1][1],
                          vB + jp * 16 * VPB + vLane + kk * 32);
                    ldsm4(bfl[pb][2 * jp][0], bfl[pb][2 * jp][1],
                          bfl[pb][2 * jp + 1][0], bfl[pb][2 * jp + 1][1],
                          vlB + jp * 16 * VPB + vLane + kk * 32);
                }
            };

            loadV(0, 0);
#pragma unroll
            for (int kk = 0; kk < 4; kk++) {
                const int pb = kk & 1;
                if (kk < 3) loadV(kk + 1, pb ^ 1);
                uint32_t a_h[4] = { ph0[2 * kk], ph1[2 * kk], ph0[2 * kk + 1], ph1[2 * kk + 1] };
                uint32_t a_l[4] = { pl0[2 * kk], pl1[2 * kk], pl0[2 * kk + 1], pl1[2 * kk + 1] };
#pragma unroll
                for (int jn = 0; jn < 8; jn++) mma16816(o[jn], a_h, bfh[pb][jn]);
#pragma unroll
                for (int jn = 0; jn < 8; jn++) mma16816(o[jn], a_h, bfl[pb][jn]);
#pragma unroll
                for (int jn = 0; jn < 8; jn++) mma16816(o[jn], a_l, bfh[pb][jn]);
            }
        }
    }

    // ---- epilogue ----
    const float inv0 = 1.f / l[0], inv1 = 1.f / l[1];
    const int t0 = qbase + wid * 16 + lr;
    const int t1 = t0 + 8;
#pragma unroll
    for (int jn = 0; jn < 8; jn++) {
        const int d = h * HD_ + jn * 8 + lq * 2;
        uint32_t hi, lo;
        split2(o[jn][0] * inv0, o[jn][1] * inv0, hi, lo);
        size_t off = (size_t)(b * T_ + t0) * D_ + d;
        *(uint32_t*)&g_ah[off] = hi; *(uint32_t*)&g_al[off] = lo;
        split2(o[jn][2] * inv1, o[jn][3] * inv1, hi, lo);
        off = (size_t)(b * T_ + t1) * D_ + d;
        *(uint32_t*)&g_ah[off] = hi; *(uint32_t*)&g_al[off] = lo;
    }
    CP_WAIT0();
}

// ======================================================================
extern "C" void kernel_launch(void* const* d_in, const int* in_sizes, int n_in,
                              void* d_out, int out_size)
{
    const float* x      = (const float*)d_in[0];
    const float* W_qkv  = (const float*)d_in[1];
    const float* b_qkv  = (const float*)d_in[2];
    const float* W_out  = (const float*)d_in[3];
    const float* b_out  = (const float*)d_in[4];
    float* out = (float*)d_out;

    __nv_bfloat16 *xh, *xl, *ah, *al, *wqh, *wql, *woh, *wol;
    cudaGetSymbolAddress((void**)&xh,  g_xh);
    cudaGetSymbolAddress((void**)&xl,  g_xl);
    cudaGetSymbolAddress((void**)&ah,  g_ah);
    cudaGetSymbolAddress((void**)&al,  g_al);
    cudaGetSymbolAddress((void**)&wqh, g_wqh);
    cudaGetSymbolAddress((void**)&wql, g_wql);
    cudaGetSymbolAddress((void**)&woh, g_woh);
    cudaGetSymbolAddress((void**)&wol, g_wol);

    cudaFuncSetAttribute(gemm_tc_mma, cudaFuncAttributeMaxDynamicSharedMemorySize, SMEM_GT);
    cudaFuncSetAttribute(attn_mma,    cudaFuncAttributeMaxDynamicSharedMemorySize, SMEM_AT);

    const int nX = B_ * T_ * D_;

    conv_split<<<(nX + 255) / 256, 256>>>(x, xh, xl, nX);
    {
        dim3 blk(32, 8);
        dim3 g1((3 * D_) / 32, D_ / 32);
        conv_split_tr<<<g1, blk>>>(W_qkv, wqh, wql, D_, 3 * D_);
        dim3 g2(D_ / 32, D_ / 32);
        conv_split_tr<<<g2, blk>>>(W_out, woh, wol, D_, D_);
    }

    {
        dim3 grid((3 * D_) / 256, (B_ * T_) / 128);
        gemm_tc_mma<<<grid, 256, SMEM_GT>>>(xh, xl, wqh, wql, b_qkv, nullptr,
                                            B_ * T_, 3 * D_, D_, 0);
    }
    {
        dim3 grid(T_ / QT, H_, B_);
        attn_mma<<<grid, 256, SMEM_AT>>>();
    }
    {
        dim3 grid(D_ / 256, (B_ * T_) / 128);
        gemm_tc_mma<<<grid, 256, SMEM_GT>>>(ah, al, woh, wol, b_out, out,
                                            B_ * T_, D_, D_, 1);
    }
}

// round 15
// speedup vs baseline: 1.1213x; 1.0263x over previous
#include <cuda_runtime.h>
#include <cuda_bf16.h>
#include <cstdint>

#define B_   2
#define T_   4096
#define D_   768
#define H_   12
#define HD_  64
#define SCALE2_ 0.1803368801f   // 0.125 * log2(e)

#define QT 64

// ---------------- scratch ----------------
__device__ __nv_bfloat16 g_qh[(size_t)B_ * H_ * T_ * HD_];   // [B,H,T,hd]
__device__ __nv_bfloat16 g_ql[(size_t)B_ * H_ * T_ * HD_];
__device__ __nv_bfloat16 g_kh[(size_t)B_ * H_ * T_ * HD_];
__device__ __nv_bfloat16 g_kl[(size_t)B_ * H_ * T_ * HD_];
__device__ __nv_bfloat16 g_vh[(size_t)B_ * H_ * T_ * HD_];   // TRANSPOSED: [B,H,hd,T]
__device__ __nv_bfloat16 g_vl[(size_t)B_ * H_ * T_ * HD_];
__device__ __nv_bfloat16 g_xh[(size_t)B_ * T_ * D_];
__device__ __nv_bfloat16 g_xl[(size_t)B_ * T_ * D_];
__device__ __nv_bfloat16 g_ah[(size_t)B_ * T_ * D_];
__device__ __nv_bfloat16 g_al[(size_t)B_ * T_ * D_];
__device__ __nv_bfloat16 g_wqh[(size_t)3 * D_ * D_];
__device__ __nv_bfloat16 g_wql[(size_t)3 * D_ * D_];
__device__ __nv_bfloat16 g_woh[(size_t)D_ * D_];
__device__ __nv_bfloat16 g_wol[(size_t)D_ * D_];

// ======================= helpers ========================
__device__ __forceinline__ uint32_t smem_u32(const void* p) {
    uint32_t a;
    asm("{ .reg .u64 t; cvta.to.shared.u64 t, %1; cvt.u32.u64 %0, t; }"
        : "=r"(a) : "l"(p));
    return a;
}

__device__ __forceinline__ void cp16(uint32_t s, const void* g) {
    asm volatile("cp.async.cg.shared.global [%0], [%1], 16;" :: "r"(s), "l"(g));
}
#define CP_COMMIT() asm volatile("cp.async.commit_group;" ::: "memory")
#define CP_WAIT1()  asm volatile("cp.async.wait_group 1;" ::: "memory")
#define CP_WAIT0()  asm volatile("cp.async.wait_group 0;" ::: "memory")

__device__ __forceinline__ void mma16816(float* c, const uint32_t* a, const uint32_t* b) {
    asm("mma.sync.aligned.m16n8k16.row.col.f32.bf16.bf16.f32 "
        "{%0,%1,%2,%3}, {%4,%5,%6,%7}, {%8,%9}, {%0,%1,%2,%3};"
        : "+f"(c[0]), "+f"(c[1]), "+f"(c[2]), "+f"(c[3])
        : "r"(a[0]), "r"(a[1]), "r"(a[2]), "r"(a[3]), "r"(b[0]), "r"(b[1]));
}

__device__ __forceinline__ void ldsm4(uint32_t& r0, uint32_t& r1,
                                      uint32_t& r2, uint32_t& r3, uint32_t a) {
    asm volatile("ldmatrix.sync.aligned.m8n8.x4.shared.b16 {%0,%1,%2,%3}, [%4];"
                 : "=r"(r0), "=r"(r1), "=r"(r2), "=r"(r3) : "r"(a));
}

__device__ __forceinline__ float ex2(float x) {
    float r;
    asm("ex2.approx.f32 %0, %1;" : "=f"(r) : "f"(x));
    return r;
}

__device__ __forceinline__ uint32_t pack_bf(__nv_bfloat16 a, __nv_bfloat16 b) {
    __nv_bfloat162 t(a, b);
    return *reinterpret_cast<uint32_t*>(&t);
}

__device__ __forceinline__ void split2(float v0, float v1, uint32_t& hi, uint32_t& lo) {
    __nv_bfloat16 h0 = __float2bfloat16_rn(v0);
    __nv_bfloat16 h1 = __float2bfloat16_rn(v1);
    float r0 = v0 - __bfloat162float(h0);
    float r1 = v1 - __bfloat162float(h1);
    hi = pack_bf(h0, h1);
    lo = pack_bf(__float2bfloat16_rn(r0), __float2bfloat16_rn(r1));
}

// ======================================================================
// conversions
// ======================================================================
__global__ void conv_split(const float* __restrict__ in,
                           __nv_bfloat16* __restrict__ oh,
                           __nv_bfloat16* __restrict__ ol, int n)
{
    int i = blockIdx.x * blockDim.x + threadIdx.x;
    if (i >= n) return;
    float v = in[i];
    __nv_bfloat16 h = __float2bfloat16_rn(v);
    float r = v - __bfloat162float(h);
    oh[i] = h;
    ol[i] = __float2bfloat16_rn(r);
}

__global__ void conv_split_tr(const float* __restrict__ in,
                              __nv_bfloat16* __restrict__ oh,
                              __nv_bfloat16* __restrict__ ol, int K, int N)
{
    __shared__ float t[32][33];
    const int bn = blockIdx.x * 32;
    const int bk = blockIdx.y * 32;
    const int tx = threadIdx.x;
    const int ty = threadIdx.y;
#pragma unroll
    for (int p = 0; p < 4; p++)
        t[ty + p * 8][tx] = in[(size_t)(bk + ty + p * 8) * N + bn + tx];
    __syncthreads();
#pragma unroll
    for (int p = 0; p < 4; p++) {
        const float v = t[tx][ty + p * 8];
        __nv_bfloat16 h = __float2bfloat16_rn(v);
        const size_t off = (size_t)(bn + ty + p * 8) * K + bk + tx;
        oh[off] = h;
        ol[off] = __float2bfloat16_rn(v - __bfloat162float(h));
    }
}

// ======================================================================
// HMMA GEMM, bf16 split. Block tile 128(M) x 32*NJ(N), 256 threads,
// 8 warps 2(M)x4(N), warp tile 64 x 8*NJ. NJ=8 -> N=256; NJ=4 -> N=128.
// ======================================================================
#define LDKB 144
#define ATILE (128 * LDKB)
#define BTILE_(NJ) (32 * (NJ) * LDKB)
#define BUFSZ_(NJ) (2 * ATILE + 2 * BTILE_(NJ))
#define SMEM_GT8 (2 * BUFSZ_(8))
#define SMEM_GT4 (2 * BUFSZ_(4))

template<int NJ>
__global__ void __launch_bounds__(256, 1) gemm_tc_mma(
    const __nv_bfloat16* __restrict__ Ah, const __nv_bfloat16* __restrict__ Al,
    const __nv_bfloat16* __restrict__ Bh, const __nv_bfloat16* __restrict__ Bl,
    const float* __restrict__ bias, float* __restrict__ Cout,
    int M, int N, int K, int mode)
{
    extern __shared__ char smc[];
    const uint32_t sbase = smem_u32(smc);
    const int tid  = threadIdx.x;
    const int lane = tid & 31;
    const int wid  = tid >> 5;
    const int wm   = wid & 1;
    const int wn   = wid >> 1;
    const int bm = blockIdx.y * 128;
    const int bn = blockIdx.x * (32 * NJ);

    const char* gA[2] = { (const char*)(Ah + (size_t)bm * K),
                          (const char*)(Al + (size_t)bm * K) };
    const char* gB[2] = { (const char*)(Bh + (size_t)bn * K),
                          (const char*)(Bl + (size_t)bn * K) };

    const int nk = K / 64;

    auto aoff = [&](int buf, int v) { return buf * BUFSZ_(NJ) + v * ATILE; };
    auto boff = [&](int buf, int v) { return buf * BUFSZ_(NJ) + 2 * ATILE + v * BTILE_(NJ); };

    auto issue_chunk = [&](int k0, int buf) {
#pragma unroll
        for (int v = 0; v < 2; v++) {
#pragma unroll
            for (int j = 0; j < 4; j++) {
                const int idx = j * 256 + tid;
                const int row = idx >> 3, c16 = idx & 7;
                cp16(sbase + aoff(buf, v) + row * LDKB + c16 * 16,
                     gA[v] + (size_t)row * (K * 2) + k0 * 2 + c16 * 16);
            }
#pragma unroll
            for (int j = 0; j < NJ; j++) {
                const int idx = j * 256 + tid;
                const int row = idx >> 3, c16 = idx & 7;
                cp16(sbase + boff(buf, v) + row * LDKB + c16 * 16,
                     gB[v] + (size_t)row * (K * 2) + k0 * 2 + c16 * 16);
            }
        }
    };

    issue_chunk(0, 0); CP_COMMIT();
    if (nk > 1) { issue_chunk(64, 1); }
    CP_COMMIT();

    float acc[4][NJ][4];
#pragma unroll
    for (int i = 0; i < 4; i++)
#pragma unroll
        for (int j = 0; j < NJ; j++)
#pragma unroll
            for (int q = 0; q < 4; q++) acc[i][j][q] = 0.f;

    const int lr = lane >> 2;
    const int lc = (lane & 3) * 2;

    const uint32_t aLane = (((lane >> 3) & 1) * 8 + (lane & 7)) * LDKB + (lane >> 4) * 16;
    const uint32_t bLane = ((lane >> 4) * 8 + (lane & 7)) * LDKB + ((lane >> 3) & 1) * 16;

    for (int it = 0; it < nk; ++it) {
        const int buf = it & 1;
        CP_WAIT1();
        __syncthreads();

        const uint32_t sA[2] = { sbase + (uint32_t)aoff(buf, 0), sbase + (uint32_t)aoff(buf, 1) };
        const uint32_t sB[2] = { sbase + (uint32_t)boff(buf, 0), sbase + (uint32_t)boff(buf, 1) };

#pragma unroll
        for (int kk = 0; kk < 4; kk++) {
            uint32_t af[2][4][4];
#pragma unroll
            for (int v = 0; v < 2; v++)
#pragma unroll
                for (int i = 0; i < 4; i++)
                    ldsm4(af[v][i][0], af[v][i][1], af[v][i][2], af[v][i][3],
                          sA[v] + (wm * 64 + i * 16) * LDKB + aLane + kk * 32);
            uint32_t bf[2][NJ][2];
#pragma unroll
            for (int v = 0; v < 2; v++)
#pragma unroll
                for (int jp = 0; jp < NJ / 2; jp++)
                    ldsm4(bf[v][2 * jp][0], bf[v][2 * jp][1],
                          bf[v][2 * jp + 1][0], bf[v][2 * jp + 1][1],
                          sB[v] + (wn * (8 * NJ) + jp * 16) * LDKB + bLane + kk * 32);
#pragma unroll
            for (int i = 0; i < 4; i++)
#pragma unroll
                for (int j = 0; j < NJ; j++)
                    mma16816(acc[i][j], af[0][i], bf[0][j]);
#pragma unroll
            for (int i = 0; i < 4; i++)
#pragma unroll
                for (int j = 0; j < NJ; j++)
                    mma16816(acc[i][j], af[0][i], bf[1][j]);
#pragma unroll
            for (int i = 0; i < 4; i++)
#pragma unroll
                for (int j = 0; j < NJ; j++)
                    mma16816(acc[i][j], af[1][i], bf[0][j]);
        }
        __syncthreads();
        if (it + 2 < nk) { issue_chunk((it + 2) * 64, buf); }
        CP_COMMIT();
    }

    // -------- epilogue --------
#pragma unroll
    for (int i = 0; i < 4; i++) {
        const int row0 = bm + wm * 64 + i * 16 + lr;
#pragma unroll
        for (int j = 0; j < NJ; j++) {
            const int col = bn + wn * (8 * NJ) + j * 8 + lc;
            const float b0 = bias[col], b1 = bias[col + 1];
            const float v00 = acc[i][j][0] + b0, v01 = acc[i][j][1] + b1;
            const float v10 = acc[i][j][2] + b0, v11 = acc[i][j][3] + b1;
            if (mode == 1) {
                *(float2*)&Cout[(size_t)row0 * N + col]       = make_float2(v00, v01);
                *(float2*)&Cout[(size_t)(row0 + 8) * N + col] = make_float2(v10, v11);
            } else {
                const int sel = col / D_;
                const int rem = col % D_;
                const int h   = rem / HD_;
                const int d0  = rem % HD_;
                const int bb0 = row0 >> 12, t0 = row0 & (T_ - 1);
                const int bb1 = (row0 + 8) >> 12, t1 = (row0 + 8) & (T_ - 1);
                if (sel == 2) {
                    const size_t hb0 = (size_t)(bb0 * H_ + h) * HD_;
                    const size_t hb1 = (size_t)(bb1 * H_ + h) * HD_;
                    __nv_bfloat16 h00 = __float2bfloat16_rn(v00);
                    __nv_bfloat16 h01 = __float2bfloat16_rn(v01);
                    __nv_bfloat16 h10 = __float2bfloat16_rn(v10);
                    __nv_bfloat16 h11 = __float2bfloat16_rn(v11);
                    g_vh[(hb0 + d0)     * T_ + t0] = h00;
                    g_vh[(hb0 + d0 + 1) * T_ + t0] = h01;
                    g_vh[(hb1 + d0)     * T_ + t1] = h10;
                    g_vh[(hb1 + d0 + 1) * T_ + t1] = h11;
                    g_vl[(hb0 + d0)     * T_ + t0] = __float2bfloat16_rn(v00 - __bfloat162float(h00));
                    g_vl[(hb0 + d0 + 1) * T_ + t0] = __float2bfloat16_rn(v01 - __bfloat162float(h01));
                    g_vl[(hb1 + d0)     * T_ + t1] = __float2bfloat16_rn(v10 - __bfloat162float(h10));
                    g_vl[(hb1 + d0 + 1) * T_ + t1] = __float2bfloat16_rn(v11 - __bfloat162float(h11));
                } else {
                    __nv_bfloat16* dh = (sel == 0) ? g_qh : g_kh;
                    __nv_bfloat16* dl = (sel == 0) ? g_ql : g_kl;
                    uint32_t hi, lo;
                    split2(v00, v01, hi, lo);
                    size_t off = ((size_t)(bb0 * H_ + h) * T_ + t0) * HD_ + d0;
                    *(uint32_t*)&dh[off] = hi; *(uint32_t*)&dl[off] = lo;
                    split2(v10, v11, hi, lo);
                    off = ((size_t)(bb1 * H_ + h) * T_ + t1) * HD_ + d0;
                    *(uint32_t*)&dh[off] = hi; *(uint32_t*)&dl[off] = lo;
                }
            }
        }
    }
    CP_WAIT0();
}

// ======================================================================
// Causal flash attention, QT=64, 128 threads, 2 CTAs/SM (cross-CTA
// softmax/MMA overlap). 2-slot cp.async ring of 64-key tiles; exp2-folded
// scale. smem: Q hi/lo 64x144 (18432) + 2 x 36864 = 92160.
// ======================================================================
#define APB 144
#define AT_KV (2 * 64 * APB)             // 18432 (Q hi/lo)
#define KVBUF (4 * 64 * APB)             // 36864 per ring slot
#define SMEM_AT (AT_KV + 2 * KVBUF)      // 92160

__global__ void __launch_bounds__(128, 2) attn_mma()
{
    extern __shared__ char sm[];
    const uint32_t sbase = smem_u32(sm);
    char* sQh = sm;
    char* sQl = sm + 64 * APB;

    const int tid = threadIdx.x, lane = tid & 31, wid = tid >> 5;  // wid 0..3
    const int lr = lane >> 2, lq = lane & 3;
    const int qi = (int)gridDim.x - 1 - (int)blockIdx.x;
    const int h = blockIdx.y, b = blockIdx.z;
    const int qbase = qi * QT;

    const size_t bh = (size_t)(b * H_ + h) * T_;
    const char* qh = (const char*)(g_qh + (bh + qbase) * HD_);
    const char* ql = (const char*)(g_ql + (bh + qbase) * HD_);
    const char* kh = (const char*)(g_kh + bh * HD_);
    const char* kl = (const char*)(g_kl + bh * HD_);
    const char* vh = (const char*)(g_vh + bh * HD_);   // [hd][T]
    const char* vl = (const char*)(g_vl + bh * HD_);

    auto stage = [&](int kb, int buf) {
        const uint32_t base = sbase + AT_KV + buf * KVBUF;
#pragma unroll
        for (int t = 0; t < 4; t++) {
            const char* src = (t == 0) ? kh : (t == 1) ? kl : (t == 2) ? vh : vl;
#pragma unroll
            for (int j = 0; j < 4; j++) {
                const int idx = j * 128 + tid;        // 0..511
                const int row = idx >> 3, c16 = idx & 7;
                const char* g = (t < 2)
                    ? src + (size_t)(kb + row) * 128 + c16 * 16
                    : src + (size_t)row * (T_ * 2) + (size_t)kb * 2 + c16 * 16;
                cp16(base + t * (64 * APB) + row * APB + c16 * 16, g);
            }
        }
    };

    const int nkt = qi + 1;

    stage(0, 0); CP_COMMIT();

    // stage Q (plain loads overlap cp.async): 64 rows x 8 c16 per plane
#pragma unroll
    for (int p = 0; p < 4; p++) {
        const int idx = p * 128 + tid;
        const int row = idx >> 3, c16 = idx & 7;
        *(uint4*)(sQh + row * APB + c16 * 16) =
            *(const uint4*)(qh + (size_t)row * 128 + c16 * 16);
        *(uint4*)(sQl + row * APB + c16 * 16) =
            *(const uint4*)(ql + (size_t)row * 128 + c16 * 16);
    }
    __syncthreads();

    // hoist Q fragments
    uint32_t qf[4][2][4];
    {
        const int r0 = (wid * 16 + lr) * APB;
#pragma unroll
        for (int kk = 0; kk < 4; kk++) {
            const int kbo = kk * 32 + lq * 4;
            qf[kk][0][0] = *(const uint32_t*)(sQh + r0 + kbo);
            qf[kk][0][1] = *(const uint32_t*)(sQh + r0 + 8 * APB + kbo);
            qf[kk][0][2] = *(const uint32_t*)(sQh + r0 + kbo + 16);
            qf[kk][0][3] = *(const uint32_t*)(sQh + r0 + 8 * APB + kbo + 16);
            qf[kk][1][0] = *(const uint32_t*)(sQl + r0 + kbo);
            qf[kk][1][1] = *(const uint32_t*)(sQl + r0 + 8 * APB + kbo);
            qf[kk][1][2] = *(const uint32_t*)(sQl + r0 + kbo + 16);
            qf[kk][1][3] = *(const uint32_t*)(sQl + r0 + 8 * APB + kbo + 16);
        }
    }

    float m[2] = {-1e30f, -1e30f}, l[2] = {0.f, 0.f};
    float o[8][4];
#pragma unroll
    for (int j = 0; j < 8; j++)
#pragma unroll
        for (int q = 0; q < 4; q++) o[j][q] = 0.f;

    const uint32_t kvLane = ((lane >> 4) * 8 + (lane & 7)) * APB + ((lane >> 3) & 1) * 16;

    uint32_t bfh[2][8][2], bfl[2][8][2];

    for (int kt = 0; kt < nkt; kt++) {
        const int kb = kt * QT;
        const int buf = kt & 1;
        const uint32_t kB  = sbase + AT_KV + buf * KVBUF;
        const uint32_t klB = kB  + 64 * APB;
        const uint32_t vB  = klB + 64 * APB;
        const uint32_t vlB = vB  + 64 * APB;

        CP_WAIT0();          // slot kt resident
        __syncthreads();     // slot (kt+1)&1 free (all warps done iter kt-1)
        if (kt + 1 < nkt) stage((kt + 1) * QT, (kt + 1) & 1);
        CP_COMMIT();

        // ---- S = Q K^T (pipelined K frags, ldmatrix) ----
        float s[8][4];
#pragma unroll
        for (int j = 0; j < 8; j++)
#pragma unroll
            for (int q = 0; q < 4; q++) s[j][q] = 0.f;

        auto loadK = [&](int kk, int pb) {
#pragma unroll
            for (int jp = 0; jp < 4; jp++) {
                ldsm4(bfh[pb][2 * jp][0], bfh[pb][2 * jp][1],
                      bfh[pb][2 * jp + 1][0], bfh[pb][2 * jp + 1][1],
                      kB + jp * 16 * APB + kvLane + kk * 32);
                ldsm4(bfl[pb][2 * jp][0], bfl[pb][2 * jp][1],
                      bfl[pb][2 * jp + 1][0], bfl[pb][2 * jp + 1][1],
                      klB + jp * 16 * APB + kvLane + kk * 32);
            }
        };

        loadK(0, 0);
#pragma unroll
        for (int kk = 0; kk < 4; kk++) {
            const int pb = kk & 1;
            if (kk < 3) loadK(kk + 1, pb ^ 1);
#pragma unroll
            for (int j = 0; j < 8; j++) mma16816(s[j], qf[kk][0], bfh[pb][j]);
#pragma unroll
            for (int j = 0; j < 8; j++) mma16816(s[j], qf[kk][0], bfl[pb][j]);
#pragma unroll
            for (int j = 0; j < 8; j++) mma16816(s[j], qf[kk][1], bfh[pb][j]);
        }

        // ---- scale (log2 domain) + causal mask ----
        const bool needmask = (kb + 63) > (qbase + wid * 16);
        if (needmask) {
            const int row_a = qbase + wid * 16 + lr;
#pragma unroll
            for (int j = 0; j < 8; j++) {
                const int col0 = kb + j * 8 + lq * 2;
                s[j][0] = (col0     <= row_a)     ? s[j][0] * SCALE2_ : -1e30f;
                s[j][1] = (col0 + 1 <= row_a)     ? s[j][1] * SCALE2_ : -1e30f;
                s[j][2] = (col0     <= row_a + 8) ? s[j][2] * SCALE2_ : -1e30f;
                s[j][3] = (col0 + 1 <= row_a + 8) ? s[j][3] * SCALE2_ : -1e30f;
            }
        } else {
#pragma unroll
            for (int j = 0; j < 8; j++)
#pragma unroll
                for (int q = 0; q < 4; q++) s[j][q] *= SCALE2_;
        }

        // ---- online softmax (base-2) ----
#pragma unroll
        for (int r = 0; r < 2; r++) {
            float mx = -1e30f;
#pragma unroll
            for (int j = 0; j < 8; j++)
                mx = fmaxf(mx, fmaxf(s[j][2 * r], s[j][2 * r + 1]));
            mx = fmaxf(mx, __shfl_xor_sync(0xffffffffu, mx, 1));
            mx = fmaxf(mx, __shfl_xor_sync(0xffffffffu, mx, 2));
            const float mnew = fmaxf(m[r], mx);
            const float corr = ex2(m[r] - mnew);
            float sum = 0.f;
#pragma unroll
            for (int j = 0; j < 8; j++) {
                const float p0 = ex2(s[j][2 * r]     - mnew);
                const float p1 = ex2(s[j][2 * r + 1] - mnew);
                s[j][2 * r] = p0; s[j][2 * r + 1] = p1;
                sum += p0 + p1;
            }
            sum += __shfl_xor_sync(0xffffffffu, sum, 1);
            sum += __shfl_xor_sync(0xffffffffu, sum, 2);
            l[r] = l[r] * corr + sum;
            m[r] = mnew;
#pragma unroll
            for (int j = 0; j < 8; j++) {
                o[j][2 * r] *= corr; o[j][2 * r + 1] *= corr;
            }
        }

        // ---- P fragments (split) ----
        uint32_t ph0[8], ph1[8], pl0[8], pl1[8];
#pragma unroll
        for (int j = 0; j < 8; j++) {
            split2(s[j][0], s[j][1], ph0[j], pl0[j]);
            split2(s[j][2], s[j][3], ph1[j], pl1[j]);
        }

        // ---- O += P V (pipelined V frags, ldmatrix) ----
        auto loadV = [&](int kk, int pb) {
#pragma unroll
            for (int jp = 0; jp < 4; jp++) {
                ldsm4(bfh[pb][2 * jp][0], bfh[pb][2 * jp][1],
                      bfh[pb][2 * jp + 1][0], bfh[pb][2 * jp + 1][1],
                      vB + jp * 16 * APB + kvLane + kk * 32);
                ldsm4(bfl[pb][2 * jp][0], bfl[pb][2 * jp][1],
                      bfl[pb][2 * jp + 1][0], bfl[pb][2 * jp + 1][1],
                      vlB + jp * 16 * APB + kvLane + kk * 32);
            }
        };

        loadV(0, 0);
#pragma unroll
        for (int kk = 0; kk < 4; kk++) {
            const int pb = kk & 1;
            if (kk < 3) loadV(kk + 1, pb ^ 1);
            uint32_t a_h[4] = { ph0[2 * kk], ph1[2 * kk], ph0[2 * kk + 1], ph1[2 * kk + 1] };
            uint32_t a_l[4] = { pl0[2 * kk], pl1[2 * kk], pl0[2 * kk + 1], pl1[2 * kk + 1] };
#pragma unroll
            for (int jn = 0; jn < 8; jn++) mma16816(o[jn], a_h, bfh[pb][jn]);
#pragma unroll
            for (int jn = 0; jn < 8; jn++) mma16816(o[jn], a_h, bfl[pb][jn]);
#pragma unroll
            for (int jn = 0; jn < 8; jn++) mma16816(o[jn], a_l, bfh[pb][jn]);
        }
    }

    // ---- epilogue ----
    const float inv0 = 1.f / l[0], inv1 = 1.f / l[1];
    const int t0 = qbase + wid * 16 + lr;
    const int t1 = t0 + 8;
#pragma unroll
    for (int jn = 0; jn < 8; jn++) {
        const int d = h * HD_ + jn * 8 + lq * 2;
        uint32_t hi, lo;
        split2(o[jn][0] * inv0, o[jn][1] * inv0, hi, lo);
        size_t off = (size_t)(b * T_ + t0) * D_ + d;
        *(uint32_t*)&g_ah[off] = hi; *(uint32_t*)&g_al[off] = lo;
        split2(o[jn][2] * inv1, o[jn][3] * inv1, hi, lo);
        off = (size_t)(b * T_ + t1) * D_ + d;
        *(uint32_t*)&g_ah[off] = hi; *(uint32_t*)&g_al[off] = lo;
    }
    CP_WAIT0();
}

// ======================================================================
extern "C" void kernel_launch(void* const* d_in, const int* in_sizes, int n_in,
                              void* d_out, int out_size)
{
    const float* x      = (const float*)d_in[0];
    const float* W_qkv  = (const float*)d_in[1];
    const float* b_qkv  = (const float*)d_in[2];
    const float* W_out  = (const float*)d_in[3];
    const float* b_out  = (const float*)d_in[4];
    float* out = (float*)d_out;

    __nv_bfloat16 *xh, *xl, *ah, *al, *wqh, *wql, *woh, *wol;
    cudaGetSymbolAddress((void**)&xh,  g_xh);
    cudaGetSymbolAddress((void**)&xl,  g_xl);
    cudaGetSymbolAddress((void**)&ah,  g_ah);
    cudaGetSymbolAddress((void**)&al,  g_al);
    cudaGetSymbolAddress((void**)&wqh, g_wqh);
    cudaGetSymbolAddress((void**)&wql, g_wql);
    cudaGetSymbolAddress((void**)&woh, g_woh);
    cudaGetSymbolAddress((void**)&wol, g_wol);

    cudaFuncSetAttribute(gemm_tc_mma<8>, cudaFuncAttributeMaxDynamicSharedMemorySize, SMEM_GT8);
    cudaFuncSetAttribute(gemm_tc_mma<4>, cudaFuncAttributeMaxDynamicSharedMemorySize, SMEM_GT4);
    cudaFuncSetAttribute(attn_mma,       cudaFuncAttributeMaxDynamicSharedMemorySize, SMEM_AT);

    const int nX = B_ * T_ * D_;

    conv_split<<<(nX + 255) / 256, 256>>>(x, xh, xl, nX);
    {
        dim3 blk(32, 8);
        dim3 g1((3 * D_) / 32, D_ / 32);
        conv_split_tr<<<g1, blk>>>(W_qkv, wqh, wql, D_, 3 * D_);
        dim3 g2(D_ / 32, D_ / 32);
        conv_split_tr<<<g2, blk>>>(W_out, woh, wol, D_, D_);
    }

    // 1) QKV projection (N-tile 256)
    {
        dim3 grid((3 * D_) / 256, (B_ * T_) / 128);
        gemm_tc_mma<8><<<grid, 256, SMEM_GT8>>>(xh, xl, wqh, wql, b_qkv, nullptr,
                                                B_ * T_, 3 * D_, D_, 0);
    }
    // 2) causal flash attention (QT=64, 2 CTAs/SM)
    {
        dim3 grid(T_ / QT, H_, B_);
        attn_mma<<<grid, 128, SMEM_AT>>>();
    }
    // 3) output projection (N-tile 128 -> 384 CTAs, better wave fit)
    {
        dim3 grid(D_ / 128, (B_ * T_) / 128);
        gemm_tc_mma<4><<<grid, 256, SMEM_GT4>>>(ah, al, woh, wol, b_out, out,
                                                B_ * T_, D_, D_, 1);
    }
}

// round 16
// speedup vs baseline: 1.2821x; 1.1435x over previous
#include <cuda_runtime.h>
#include <cuda_bf16.h>
#include <cuda_fp16.h>
#include <cstdint>

#define B_   2
#define T_   4096
#define D_   768
#define H_   12
#define HD_  64
#define SCALE2_ 0.1803368801f   // 0.125 * log2(e)

#define QT 64

// ---------------- scratch ----------------
__device__ __half g_qh[(size_t)B_ * H_ * T_ * HD_];   // [B,H,T,hd] fp16 hi only
__device__ __half g_kh[(size_t)B_ * H_ * T_ * HD_];   // fp16 hi
__device__ __half g_kl[(size_t)B_ * H_ * T_ * HD_];   // fp16 residual
__device__ __half g_vh[(size_t)B_ * H_ * T_ * HD_];   // TRANSPOSED [B,H,hd,T], fp16 hi
__device__ __half g_vl[(size_t)B_ * H_ * T_ * HD_];   // fp16 residual
__device__ __nv_bfloat16 g_xh[(size_t)B_ * T_ * D_];
__device__ __nv_bfloat16 g_xl[(size_t)B_ * T_ * D_];
__device__ __nv_bfloat16 g_ah[(size_t)B_ * T_ * D_];
__device__ __nv_bfloat16 g_al[(size_t)B_ * T_ * D_];
__device__ __nv_bfloat16 g_wqh[(size_t)3 * D_ * D_];
__device__ __nv_bfloat16 g_wql[(size_t)3 * D_ * D_];
__device__ __nv_bfloat16 g_woh[(size_t)D_ * D_];
__device__ __nv_bfloat16 g_wol[(size_t)D_ * D_];

// ======================= helpers ========================
__device__ __forceinline__ uint32_t smem_u32(const void* p) {
    uint32_t a;
    asm("{ .reg .u64 t; cvta.to.shared.u64 t, %1; cvt.u32.u64 %0, t; }"
        : "=r"(a) : "l"(p));
    return a;
}

__device__ __forceinline__ void cp16(uint32_t s, const void* g) {
    asm volatile("cp.async.cg.shared.global [%0], [%1], 16;" :: "r"(s), "l"(g));
}
#define CP_COMMIT() asm volatile("cp.async.commit_group;" ::: "memory")
#define CP_WAIT1()  asm volatile("cp.async.wait_group 1;" ::: "memory")
#define CP_WAIT0()  asm volatile("cp.async.wait_group 0;" ::: "memory")

// bf16 HMMA
__device__ __forceinline__ void mma16816(float* c, const uint32_t* a, const uint32_t* b) {
    asm("mma.sync.aligned.m16n8k16.row.col.f32.bf16.bf16.f32 "
        "{%0,%1,%2,%3}, {%4,%5,%6,%7}, {%8,%9}, {%0,%1,%2,%3};"
        : "+f"(c[0]), "+f"(c[1]), "+f"(c[2]), "+f"(c[3])
        : "r"(a[0]), "r"(a[1]), "r"(a[2]), "r"(a[3]), "r"(b[0]), "r"(b[1]));
}

// fp16 HMMA
__device__ __forceinline__ void mma16816h(float* c, const uint32_t* a, const uint32_t* b) {
    asm("mma.sync.aligned.m16n8k16.row.col.f32.f16.f16.f32 "
        "{%0,%1,%2,%3}, {%4,%5,%6,%7}, {%8,%9}, {%0,%1,%2,%3};"
        : "+f"(c[0]), "+f"(c[1]), "+f"(c[2]), "+f"(c[3])
        : "r"(a[0]), "r"(a[1]), "r"(a[2]), "r"(a[3]), "r"(b[0]), "r"(b[1]));
}

__device__ __forceinline__ void ldsm4(uint32_t& r0, uint32_t& r1,
                                      uint32_t& r2, uint32_t& r3, uint32_t a) {
    asm volatile("ldmatrix.sync.aligned.m8n8.x4.shared.b16 {%0,%1,%2,%3}, [%4];"
                 : "=r"(r0), "=r"(r1), "=r"(r2), "=r"(r3) : "r"(a));
}

__device__ __forceinline__ float ex2(float x) {
    float r;
    asm("ex2.approx.f32 %0, %1;" : "=f"(r) : "f"(x));
    return r;
}

__device__ __forceinline__ uint32_t pack_bf(__nv_bfloat16 a, __nv_bfloat16 b) {
    __nv_bfloat162 t(a, b);
    return *reinterpret_cast<uint32_t*>(&t);
}

__device__ __forceinline__ void split2(float v0, float v1, uint32_t& hi, uint32_t& lo) {
    __nv_bfloat16 h0 = __float2bfloat16_rn(v0);
    __nv_bfloat16 h1 = __float2bfloat16_rn(v1);
    float r0 = v0 - __bfloat162float(h0);
    float r1 = v1 - __bfloat162float(h1);
    hi = pack_bf(h0, h1);
    lo = pack_bf(__float2bfloat16_rn(r0), __float2bfloat16_rn(r1));
}

__device__ __forceinline__ uint32_t pack_h(float a, float b) {
    __half2 t(__float2half_rn(a), __float2half_rn(b));
    return *reinterpret_cast<uint32_t*>(&t);
}

__device__ __forceinline__ void split2h(float v0, float v1, uint32_t& hi, uint32_t& lo) {
    __half h0 = __float2half_rn(v0);
    __half h1 = __float2half_rn(v1);
    float r0 = v0 - __half2float(h0);
    float r1 = v1 - __half2float(h1);
    __half2 H(h0, h1);
    hi = *reinterpret_cast<uint32_t*>(&H);
    __half2 L(__float2half_rn(r0), __float2half_rn(r1));
    lo = *reinterpret_cast<uint32_t*>(&L);
}

// ======================================================================
// conversions
// ======================================================================
__global__ void conv_split(const float* __restrict__ in,
                           __nv_bfloat16* __restrict__ oh,
                           __nv_bfloat16* __restrict__ ol, int n)
{
    int i = blockIdx.x * blockDim.x + threadIdx.x;
    if (i >= n) return;
    float v = in[i];
    __nv_bfloat16 h = __float2bfloat16_rn(v);
    float r = v - __bfloat162float(h);
    oh[i] = h;
    ol[i] = __float2bfloat16_rn(r);
}

__global__ void conv_split_tr(const float* __restrict__ in,
                              __nv_bfloat16* __restrict__ oh,
                              __nv_bfloat16* __restrict__ ol, int K, int N)
{
    __shared__ float t[32][33];
    const int bn = blockIdx.x * 32;
    const int bk = blockIdx.y * 32;
    const int tx = threadIdx.x;
    const int ty = threadIdx.y;
#pragma unroll
    for (int p = 0; p < 4; p++)
        t[ty + p * 8][tx] = in[(size_t)(bk + ty + p * 8) * N + bn + tx];
    __syncthreads();
#pragma unroll
    for (int p = 0; p < 4; p++) {
        const float v = t[tx][ty + p * 8];
        __nv_bfloat16 h = __float2bfloat16_rn(v);
        const size_t off = (size_t)(bn + ty + p * 8) * K + bk + tx;
        oh[off] = h;
        ol[off] = __float2bfloat16_rn(v - __bfloat162float(h));
    }
}

// ======================================================================
// HMMA GEMM, bf16 split, block tile 128 x 32*NJ. (R15 structure; mode-0
// epilogue now emits fp16 q (hi) / k (hi,lo) / v^T (hi,lo).)
// ======================================================================
#define LDKB 144
#define ATILE (128 * LDKB)
#define BTILE_(NJ) (32 * (NJ) * LDKB)
#define BUFSZ_(NJ) (2 * ATILE + 2 * BTILE_(NJ))
#define SMEM_GT8 (2 * BUFSZ_(8))
#define SMEM_GT4 (2 * BUFSZ_(4))

template<int NJ>
__global__ void __launch_bounds__(256, 1) gemm_tc_mma(
    const __nv_bfloat16* __restrict__ Ah, const __nv_bfloat16* __restrict__ Al,
    const __nv_bfloat16* __restrict__ Bh, const __nv_bfloat16* __restrict__ Bl,
    const float* __restrict__ bias, float* __restrict__ Cout,
    int M, int N, int K, int mode)
{
    extern __shared__ char smc[];
    const uint32_t sbase = smem_u32(smc);
    const int tid  = threadIdx.x;
    const int lane = tid & 31;
    const int wid  = tid >> 5;
    const int wm   = wid & 1;
    const int wn   = wid >> 1;
    const int bm = blockIdx.y * 128;
    const int bn = blockIdx.x * (32 * NJ);

    const char* gA[2] = { (const char*)(Ah + (size_t)bm * K),
                          (const char*)(Al + (size_t)bm * K) };
    const char* gB[2] = { (const char*)(Bh + (size_t)bn * K),
                          (const char*)(Bl + (size_t)bn * K) };

    const int nk = K / 64;

    auto aoff = [&](int buf, int v) { return buf * BUFSZ_(NJ) + v * ATILE; };
    auto boff = [&](int buf, int v) { return buf * BUFSZ_(NJ) + 2 * ATILE + v * BTILE_(NJ); };

    auto issue_chunk = [&](int k0, int buf) {
#pragma unroll
        for (int v = 0; v < 2; v++) {
#pragma unroll
            for (int j = 0; j < 4; j++) {
                const int idx = j * 256 + tid;
                const int row = idx >> 3, c16 = idx & 7;
                cp16(sbase + aoff(buf, v) + row * LDKB + c16 * 16,
                     gA[v] + (size_t)row * (K * 2) + k0 * 2 + c16 * 16);
            }
#pragma unroll
            for (int j = 0; j < NJ; j++) {
                const int idx = j * 256 + tid;
                const int row = idx >> 3, c16 = idx & 7;
                cp16(sbase + boff(buf, v) + row * LDKB + c16 * 16,
                     gB[v] + (size_t)row * (K * 2) + k0 * 2 + c16 * 16);
            }
        }
    };

    issue_chunk(0, 0); CP_COMMIT();
    if (nk > 1) { issue_chunk(64, 1); }
    CP_COMMIT();

    float acc[4][NJ][4];
#pragma unroll
    for (int i = 0; i < 4; i++)
#pragma unroll
        for (int j = 0; j < NJ; j++)
#pragma unroll
            for (int q = 0; q < 4; q++) acc[i][j][q] = 0.f;

    const int lr = lane >> 2;
    const int lc = (lane & 3) * 2;

    const uint32_t aLane = (((lane >> 3) & 1) * 8 + (lane & 7)) * LDKB + (lane >> 4) * 16;
    const uint32_t bLane = ((lane >> 4) * 8 + (lane & 7)) * LDKB + ((lane >> 3) & 1) * 16;

    for (int it = 0; it < nk; ++it) {
        const int buf = it & 1;
        CP_WAIT1();
        __syncthreads();

        const uint32_t sA[2] = { sbase + (uint32_t)aoff(buf, 0), sbase + (uint32_t)aoff(buf, 1) };
        const uint32_t sB[2] = { sbase + (uint32_t)boff(buf, 0), sbase + (uint32_t)boff(buf, 1) };

#pragma unroll
        for (int kk = 0; kk < 4; kk++) {
            uint32_t af[2][4][4];
#pragma unroll
            for (int v = 0; v < 2; v++)
#pragma unroll
                for (int i = 0; i < 4; i++)
                    ldsm4(af[v][i][0], af[v][i][1], af[v][i][2], af[v][i][3],
                          sA[v] + (wm * 64 + i * 16) * LDKB + aLane + kk * 32);
            uint32_t bf[2][NJ][2];
#pragma unroll
            for (int v = 0; v < 2; v++)
#pragma unroll
                for (int jp = 0; jp < NJ / 2; jp++)
                    ldsm4(bf[v][2 * jp][0], bf[v][2 * jp][1],
                          bf[v][2 * jp + 1][0], bf[v][2 * jp + 1][1],
                          sB[v] + (wn * (8 * NJ) + jp * 16) * LDKB + bLane + kk * 32);
#pragma unroll
            for (int i = 0; i < 4; i++)
#pragma unroll
                for (int j = 0; j < NJ; j++)
                    mma16816(acc[i][j], af[0][i], bf[0][j]);
#pragma unroll
            for (int i = 0; i < 4; i++)
#pragma unroll
                for (int j = 0; j < NJ; j++)
                    mma16816(acc[i][j], af[0][i], bf[1][j]);
#pragma unroll
            for (int i = 0; i < 4; i++)
#pragma unroll
                for (int j = 0; j < NJ; j++)
                    mma16816(acc[i][j], af[1][i], bf[0][j]);
        }
        __syncthreads();
        if (it + 2 < nk) { issue_chunk((it + 2) * 64, buf); }
        CP_COMMIT();
    }

    // -------- epilogue --------
#pragma unroll
    for (int i = 0; i < 4; i++) {
        const int row0 = bm + wm * 64 + i * 16 + lr;
#pragma unroll
        for (int j = 0; j < NJ; j++) {
            const int col = bn + wn * (8 * NJ) + j * 8 + lc;
            const float b0 = bias[col], b1 = bias[col + 1];
            const float v00 = acc[i][j][0] + b0, v01 = acc[i][j][1] + b1;
            const float v10 = acc[i][j][2] + b0, v11 = acc[i][j][3] + b1;
            if (mode == 1) {
                *(float2*)&Cout[(size_t)row0 * N + col]       = make_float2(v00, v01);
                *(float2*)&Cout[(size_t)(row0 + 8) * N + col] = make_float2(v10, v11);
            } else {
                const int sel = col / D_;
                const int rem = col % D_;
                const int h   = rem / HD_;
                const int d0  = rem % HD_;
                const int bb0 = row0 >> 12, t0 = row0 & (T_ - 1);
                const int bb1 = (row0 + 8) >> 12, t1 = (row0 + 8) & (T_ - 1);
                if (sel == 2) {
                    // V transposed [B,H,hd,T], fp16 hi/lo
                    const size_t hb0 = (size_t)(bb0 * H_ + h) * HD_;
                    const size_t hb1 = (size_t)(bb1 * H_ + h) * HD_;
                    __half h00 = __float2half_rn(v00);
                    __half h01 = __float2half_rn(v01);
                    __half h10 = __float2half_rn(v10);
                    __half h11 = __float2half_rn(v11);
                    g_vh[(hb0 + d0)     * T_ + t0] = h00;
                    g_vh[(hb0 + d0 + 1) * T_ + t0] = h01;
                    g_vh[(hb1 + d0)     * T_ + t1] = h10;
                    g_vh[(hb1 + d0 + 1) * T_ + t1] = h11;
                    g_vl[(hb0 + d0)     * T_ + t0] = __float2half_rn(v00 - __half2float(h00));
                    g_vl[(hb0 + d0 + 1) * T_ + t0] = __float2half_rn(v01 - __half2float(h01));
                    g_vl[(hb1 + d0)     * T_ + t1] = __float2half_rn(v10 - __half2float(h10));
                    g_vl[(hb1 + d0 + 1) * T_ + t1] = __float2half_rn(v11 - __half2float(h11));
                } else if (sel == 0) {
                    // Q: fp16 hi only
                    size_t off = ((size_t)(bb0 * H_ + h) * T_ + t0) * HD_ + d0;
                    *(uint32_t*)&g_qh[off] = pack_h(v00, v01);
                    off = ((size_t)(bb1 * H_ + h) * T_ + t1) * HD_ + d0;
                    *(uint32_t*)&g_qh[off] = pack_h(v10, v11);
                } else {
                    // K: fp16 hi/lo split
                    uint32_t hi, lo;
                    split2h(v00, v01, hi, lo);
                    size_t off = ((size_t)(bb0 * H_ + h) * T_ + t0) * HD_ + d0;
                    *(uint32_t*)&g_kh[off] = hi; *(uint32_t*)&g_kl[off] = lo;
                    split2h(v10, v11, hi, lo);
                    off = ((size_t)(bb1 * H_ + h) * T_ + t1) * HD_ + d0;
                    *(uint32_t*)&g_kh[off] = hi; *(uint32_t*)&g_kl[off] = lo;
                }
            }
        }
    }
    CP_WAIT0();
}

// ======================================================================
// Causal flash attention, fp16 2-product: S = qh*kh + qh*kl,
// O += p*vh + p*vl (p single fp16). QT=64, 128 thr, 2 CTAs/SM.
// smem: Q hi 64x144 (9216) + 2 slots x (kh,kl,vh,vl 64x144 ea) = 82944.
// ======================================================================
#define APB 144
#define AT_KV (64 * APB)                 // 9216 (Q hi only)
#define KVBUF (4 * 64 * APB)             // 36864 per ring slot
#define SMEM_AT (AT_KV + 2 * KVBUF)      // 82944

__global__ void __launch_bounds__(128, 2) attn_mma()
{
    extern __shared__ char sm[];
    const uint32_t sbase = smem_u32(sm);
    char* sQh = sm;

    const int tid = threadIdx.x, lane = tid & 31, wid = tid >> 5;  // wid 0..3
    const int lr = lane >> 2, lq = lane & 3;
    const int qi = (int)gridDim.x - 1 - (int)blockIdx.x;
    const int h = blockIdx.y, b = blockIdx.z;
    const int qbase = qi * QT;

    const size_t bh = (size_t)(b * H_ + h) * T_;
    const char* qh = (const char*)(g_qh + (bh + qbase) * HD_);
    const char* kh = (const char*)(g_kh + bh * HD_);
    const char* kl = (const char*)(g_kl + bh * HD_);
    const char* vh = (const char*)(g_vh + bh * HD_);   // [hd][T]
    const char* vl = (const char*)(g_vl + bh * HD_);

    auto stage = [&](int kb, int buf) {
        const uint32_t base = sbase + AT_KV + buf * KVBUF;
#pragma unroll
        for (int t = 0; t < 4; t++) {
            const char* src = (t == 0) ? kh : (t == 1) ? kl : (t == 2) ? vh : vl;
#pragma unroll
            for (int j = 0; j < 4; j++) {
                const int idx = j * 128 + tid;        // 0..511
                const int row = idx >> 3, c16 = idx & 7;
                const char* g = (t < 2)
                    ? src + (size_t)(kb + row) * 128 + c16 * 16
                    : src + (size_t)row * (T_ * 2) + (size_t)kb * 2 + c16 * 16;
                cp16(base + t * (64 * APB) + row * APB + c16 * 16, g);
            }
        }
    };

    const int nkt = qi + 1;

    stage(0, 0); CP_COMMIT();

    // stage Q hi (plain loads overlap cp.async): 64 rows x 8 c16
#pragma unroll
    for (int p = 0; p < 4; p++) {
        const int idx = p * 128 + tid;
        const int row = idx >> 3, c16 = idx & 7;
        *(uint4*)(sQh + row * APB + c16 * 16) =
            *(const uint4*)(qh + (size_t)row * 128 + c16 * 16);
    }
    __syncthreads();

    // hoist Q fragments (hi only)
    uint32_t qf[4][4];
    {
        const int r0 = (wid * 16 + lr) * APB;
#pragma unroll
        for (int kk = 0; kk < 4; kk++) {
            const int kbo = kk * 32 + lq * 4;
            qf[kk][0] = *(const uint32_t*)(sQh + r0 + kbo);
            qf[kk][1] = *(const uint32_t*)(sQh + r0 + 8 * APB + kbo);
            qf[kk][2] = *(const uint32_t*)(sQh + r0 + kbo + 16);
            qf[kk][3] = *(const uint32_t*)(sQh + r0 + 8 * APB + kbo + 16);
        }
    }

    float m[2] = {-1e30f, -1e30f}, l[2] = {0.f, 0.f};
    float o[8][4];
#pragma unroll
    for (int j = 0; j < 8; j++)
#pragma unroll
        for (int q = 0; q < 4; q++) o[j][q] = 0.f;

    const uint32_t kvLane = ((lane >> 4) * 8 + (lane & 7)) * APB + ((lane >> 3) & 1) * 16;

    uint32_t bfh[2][8][2], bfl[2][8][2];

    for (int kt = 0; kt < nkt; kt++) {
        const int kb = kt * QT;
        const int buf = kt & 1;
        const uint32_t kB  = sbase + AT_KV + buf * KVBUF;
        const uint32_t klB = kB  + 64 * APB;
        const uint32_t vB  = klB + 64 * APB;
        const uint32_t vlB = vB  + 64 * APB;

        CP_WAIT0();
        __syncthreads();
        if (kt + 1 < nkt) stage((kt + 1) * QT, (kt + 1) & 1);
        CP_COMMIT();

        // ---- S = Qh*Kh + Qh*Kl (fp16, 2 products) ----
        float s[8][4];
#pragma unroll
        for (int j = 0; j < 8; j++)
#pragma unroll
            for (int q = 0; q < 4; q++) s[j][q] = 0.f;

        auto loadK = [&](int kk, int pb) {
#pragma unroll
            for (int jp = 0; jp < 4; jp++) {
                ldsm4(bfh[pb][2 * jp][0], bfh[pb][2 * jp][1],
                      bfh[pb][2 * jp + 1][0], bfh[pb][2 * jp + 1][1],
                      kB + jp * 16 * APB + kvLane + kk * 32);
                ldsm4(bfl[pb][2 * jp][0], bfl[pb][2 * jp][1],
                      bfl[pb][2 * jp + 1][0], bfl[pb][2 * jp + 1][1],
                      klB + jp * 16 * APB + kvLane + kk * 32);
            }
        };

        loadK(0, 0);
#pragma unroll
        for (int kk = 0; kk < 4; kk++) {
            const int pb = kk & 1;
            if (kk < 3) loadK(kk + 1, pb ^ 1);
#pragma unroll
            for (int j = 0; j < 8; j++) mma16816h(s[j], qf[kk], bfh[pb][j]);
#pragma unroll
            for (int j = 0; j < 8; j++) mma16816h(s[j], qf[kk], bfl[pb][j]);
        }

        // ---- scale (log2 domain) + causal mask ----
        const bool needmask = (kb + 63) > (qbase + wid * 16);
        if (needmask) {
            const int row_a = qbase + wid * 16 + lr;
#pragma unroll
            for (int j = 0; j < 8; j++) {
                const int col0 = kb + j * 8 + lq * 2;
                s[j][0] = (col0     <= row_a)     ? s[j][0] * SCALE2_ : -1e30f;
                s[j][1] = (col0 + 1 <= row_a)     ? s[j][1] * SCALE2_ : -1e30f;
                s[j][2] = (col0     <= row_a + 8) ? s[j][2] * SCALE2_ : -1e30f;
                s[j][3] = (col0 + 1 <= row_a + 8) ? s[j][3] * SCALE2_ : -1e30f;
            }
        } else {
#pragma unroll
            for (int j = 0; j < 8; j++)
#pragma unroll
                for (int q = 0; q < 4; q++) s[j][q] *= SCALE2_;
        }

        // ---- online softmax (base-2) ----
#pragma unroll
        for (int r = 0; r < 2; r++) {
            float mx = -1e30f;
#pragma unroll
            for (int j = 0; j < 8; j++)
                mx = fmaxf(mx, fmaxf(s[j][2 * r], s[j][2 * r + 1]));
            mx = fmaxf(mx, __shfl_xor_sync(0xffffffffu, mx, 1));
            mx = fmaxf(mx, __shfl_xor_sync(0xffffffffu, mx, 2));
            const float mnew = fmaxf(m[r], mx);
            const float corr = ex2(m[r] - mnew);
            float sum = 0.f;
#pragma unroll
            for (int j = 0; j < 8; j++) {
                const float p0 = ex2(s[j][2 * r]     - mnew);
                const float p1 = ex2(s[j][2 * r + 1] - mnew);
                s[j][2 * r] = p0; s[j][2 * r + 1] = p1;
                sum += p0 + p1;
            }
            sum += __shfl_xor_sync(0xffffffffu, sum, 1);
            sum += __shfl_xor_sync(0xffffffffu, sum, 2);
            l[r] = l[r] * corr + sum;
            m[r] = mnew;
#pragma unroll
            for (int j = 0; j < 8; j++) {
                o[j][2 * r] *= corr; o[j][2 * r + 1] *= corr;
            }
        }

        // ---- P fragments: single fp16 (no split) ----
        uint32_t ph0[8], ph1[8];
#pragma unroll
        for (int j = 0; j < 8; j++) {
            ph0[j] = pack_h(s[j][0], s[j][1]);
            ph1[j] = pack_h(s[j][2], s[j][3]);
        }

        // ---- O += P*Vh + P*Vl (fp16, 2 products) ----
        auto loadV = [&](int kk, int pb) {
#pragma unroll
            for (int jp = 0; jp < 4; jp++) {
                ldsm4(bfh[pb][2 * jp][0], bfh[pb][2 * jp][1],
                      bfh[pb][2 * jp + 1][0], bfh[pb][2 * jp + 1][1],
                      vB + jp * 16 * APB + kvLane + kk * 32);
                ldsm4(bfl[pb][2 * jp][0], bfl[pb][2 * jp][1],
                      bfl[pb][2 * jp + 1][0], bfl[pb][2 * jp + 1][1],
                      vlB + jp * 16 * APB + kvLane + kk * 32);
            }
        };

        loadV(0, 0);
#pragma unroll
        for (int kk = 0; kk < 4; kk++) {
            const int pb = kk & 1;
            if (kk < 3) loadV(kk + 1, pb ^ 1);
            uint32_t a_h[4] = { ph0[2 * kk], ph1[2 * kk], ph0[2 * kk + 1], ph1[2 * kk + 1] };
#pragma unroll
            for (int jn = 0; jn < 8; jn++) mma16816h(o[jn], a_h, bfh[pb][jn]);
#pragma unroll
            for (int jn = 0; jn < 8; jn++) mma16816h(o[jn], a_h, bfl[pb][jn]);
        }
    }

    // ---- epilogue: normalize, bf16 split-write to g_ah/g_al [B,T,D] ----
    const float inv0 = 1.f / l[0], inv1 = 1.f / l[1];
    const int t0 = qbase + wid * 16 + lr;
    const int t1 = t0 + 8;
#pragma unroll
    for (int jn = 0; jn < 8; jn++) {
        const int d = h * HD_ + jn * 8 + lq * 2;
        uint32_t hi, lo;
        split2(o[jn][0] * inv0, o[jn][1] * inv0, hi, lo);
        size_t off = (size_t)(b * T_ + t0) * D_ + d;
        *(uint32_t*)&g_ah[off] = hi; *(uint32_t*)&g_al[off] = lo;
        split2(o[jn][2] * inv1, o[jn][3] * inv1, hi, lo);
        off = (size_t)(b * T_ + t1) * D_ + d;
        *(uint32_t*)&g_ah[off] = hi; *(uint32_t*)&g_al[off] = lo;
    }
    CP_WAIT0();
}

// ======================================================================
extern "C" void kernel_launch(void* const* d_in, const int* in_sizes, int n_in,
                              void* d_out, int out_size)
{
    const float* x      = (const float*)d_in[0];
    const float* W_qkv  = (const float*)d_in[1];
    const float* b_qkv  = (const float*)d_in[2];
    const float* W_out  = (const float*)d_in[3];
    const float* b_out  = (const float*)d_in[4];
    float* out = (float*)d_out;

    __nv_bfloat16 *xh, *xl, *ah, *al, *wqh, *wql, *woh, *wol;
    cudaGetSymbolAddress((void**)&xh,  g_xh);
    cudaGetSymbolAddress((void**)&xl,  g_xl);
    cudaGetSymbolAddress((void**)&ah,  g_ah);
    cudaGetSymbolAddress((void**)&al,  g_al);
    cudaGetSymbolAddress((void**)&wqh, g_wqh);
    cudaGetSymbolAddress((void**)&wql, g_wql);
    cudaGetSymbolAddress((void**)&woh, g_woh);
    cudaGetSymbolAddress((void**)&wol, g_wol);

    cudaFuncSetAttribute(gemm_tc_mma<8>, cudaFuncAttributeMaxDynamicSharedMemorySize, SMEM_GT8);
    cudaFuncSetAttribute(gemm_tc_mma<4>, cudaFuncAttributeMaxDynamicSharedMemorySize, SMEM_GT4);
    cudaFuncSetAttribute(attn_mma,       cudaFuncAttributeMaxDynamicSharedMemorySize, SMEM_AT);

    const int nX = B_ * T_ * D_;

    conv_split<<<(nX + 255) / 256, 256>>>(x, xh, xl, nX);
    {
        dim3 blk(32, 8);
        dim3 g1((3 * D_) / 32, D_ / 32);
        conv_split_tr<<<g1, blk>>>(W_qkv, wqh, wql, D_, 3 * D_);
        dim3 g2(D_ / 32, D_ / 32);
        conv_split_tr<<<g2, blk>>>(W_out, woh, wol, D_, D_);
    }

    // 1) QKV projection (N-tile 256)
    {
        dim3 grid((3 * D_) / 256, (B_ * T_) / 128);
        gemm_tc_mma<8><<<grid, 256, SMEM_GT8>>>(xh, xl, wqh, wql, b_qkv, nullptr,
                                                B_ * T_, 3 * D_, D_, 0);
    }
    // 2) causal flash attention (fp16 2-product, QT=64, 2 CTAs/SM)
    {
        dim3 grid(T_ / QT, H_, B_);
        attn_mma<<<grid, 128, SMEM_AT>>>();
    }
    // 3) output projection (N-tile 128)
    {
        dim3 grid(D_ / 128, (B_ * T_) / 128);
        gemm_tc_mma<4><<<grid, 256, SMEM_GT4>>>(ah, al, woh, wol, b_out, out,
                                                B_ * T_, D_, D_, 1);
    }
}

// round 17
// speedup vs baseline: 1.4502x; 1.1311x over previous
#include <cuda_runtime.h>
#include <cuda_bf16.h>
#include <cuda_fp16.h>
#include <cstdint>

#define B_   2
#define T_   4096
#define D_   768
#define H_   12
#define HD_  64
#define SCALE2_ 0.1803368801f   // 0.125 * log2(e)

#define QT 64

// ---------------- scratch ----------------
__device__ __half g_qh[(size_t)B_ * H_ * T_ * HD_];   // [B,H,T,hd] fp16 hi only
__device__ __half g_kh[(size_t)B_ * H_ * T_ * HD_];   // fp16 hi
__device__ __half g_kl[(size_t)B_ * H_ * T_ * HD_];   // fp16 residual
__device__ __half g_vh[(size_t)B_ * H_ * T_ * HD_];   // TRANSPOSED [B,H,hd,T], fp16 hi
__device__ __half g_vl[(size_t)B_ * H_ * T_ * HD_];   // fp16 residual
__device__ __half g_x16[(size_t)B_ * T_ * D_];        // x,  fp16 (GEMM A)
__device__ __half g_a16[(size_t)B_ * T_ * D_];        // attn out, fp16 (GEMM A)
__device__ __half g_wqh[(size_t)3 * D_ * D_];         // W_qkv^T fp16 hi
__device__ __half g_wql[(size_t)3 * D_ * D_];         // W_qkv^T fp16 residual
__device__ __half g_woh[(size_t)D_ * D_];             // W_out^T fp16 hi
__device__ __half g_wol[(size_t)D_ * D_];             // W_out^T fp16 residual

// ======================= helpers ========================
__device__ __forceinline__ uint32_t smem_u32(const void* p) {
    uint32_t a;
    asm("{ .reg .u64 t; cvta.to.shared.u64 t, %1; cvt.u32.u64 %0, t; }"
        : "=r"(a) : "l"(p));
    return a;
}

__device__ __forceinline__ void cp16(uint32_t s, const void* g) {
    asm volatile("cp.async.cg.shared.global [%0], [%1], 16;" :: "r"(s), "l"(g));
}
#define CP_COMMIT() asm volatile("cp.async.commit_group;" ::: "memory")
#define CP_WAIT1()  asm volatile("cp.async.wait_group 1;" ::: "memory")
#define CP_WAIT0()  asm volatile("cp.async.wait_group 0;" ::: "memory")

// fp16 HMMA
__device__ __forceinline__ void mma16816h(float* c, const uint32_t* a, const uint32_t* b) {
    asm("mma.sync.aligned.m16n8k16.row.col.f32.f16.f16.f32 "
        "{%0,%1,%2,%3}, {%4,%5,%6,%7}, {%8,%9}, {%0,%1,%2,%3};"
        : "+f"(c[0]), "+f"(c[1]), "+f"(c[2]), "+f"(c[3])
        : "r"(a[0]), "r"(a[1]), "r"(a[2]), "r"(a[3]), "r"(b[0]), "r"(b[1]));
}

__device__ __forceinline__ void ldsm4(uint32_t& r0, uint32_t& r1,
                                      uint32_t& r2, uint32_t& r3, uint32_t a) {
    asm volatile("ldmatrix.sync.aligned.m8n8.x4.shared.b16 {%0,%1,%2,%3}, [%4];"
                 : "=r"(r0), "=r"(r1), "=r"(r2), "=r"(r3) : "r"(a));
}

__device__ __forceinline__ float ex2(float x) {
    float r;
    asm("ex2.approx.f32 %0, %1;" : "=f"(r) : "f"(x));
    return r;
}

__device__ __forceinline__ uint32_t pack_h(float a, float b) {
    __half2 t(__float2half_rn(a), __float2half_rn(b));
    return *reinterpret_cast<uint32_t*>(&t);
}

__device__ __forceinline__ void split2h(float v0, float v1, uint32_t& hi, uint32_t& lo) {
    __half h0 = __float2half_rn(v0);
    __half h1 = __float2half_rn(v1);
    float r0 = v0 - __half2float(h0);
    float r1 = v1 - __half2float(h1);
    __half2 H(h0, h1);
    hi = *reinterpret_cast<uint32_t*>(&H);
    __half2 L(__float2half_rn(r0), __float2half_rn(r1));
    lo = *reinterpret_cast<uint32_t*>(&L);
}

// ======================================================================
// conversions
// ======================================================================
__global__ void conv_h(const float* __restrict__ in,
                       __half* __restrict__ o, int n)
{
    int i = blockIdx.x * blockDim.x + threadIdx.x;
    if (i >= n) return;
    o[i] = __float2half_rn(in[i]);
}

// coalesced tiled transpose-split: in[K][N] fp32 -> oh/ol[N][K] fp16
__global__ void conv_split_tr(const float* __restrict__ in,
                              __half* __restrict__ oh,
                              __half* __restrict__ ol, int K, int N)
{
    __shared__ float t[32][33];
    const int bn = blockIdx.x * 32;
    const int bk = blockIdx.y * 32;
    const int tx = threadIdx.x;
    const int ty = threadIdx.y;
#pragma unroll
    for (int p = 0; p < 4; p++)
        t[ty + p * 8][tx] = in[(size_t)(bk + ty + p * 8) * N + bn + tx];
    __syncthreads();
#pragma unroll
    for (int p = 0; p < 4; p++) {
        const float v = t[tx][ty + p * 8];
        __half h = __float2half_rn(v);
        const size_t off = (size_t)(bn + ty + p * 8) * K + bk + tx;
        oh[off] = h;
        ol[off] = __float2half_rn(v - __half2float(h));
    }
}

// ======================================================================
// HMMA GEMM, fp16 2-product: C = A(fp16) @ (Bh+Bl)^T + bias.
// Block tile 128 x 32*NJ, 256 threads, 8 warps 2x4, warp tile 64 x 8*NJ.
// mode 0 -> scatter fp16 q (hi) / k (hi,lo) / v^T (hi,lo); mode 1 -> fp32.
// ======================================================================
#define LDKB 144
#define ATILE (128 * LDKB)
#define BTILE_(NJ) (32 * (NJ) * LDKB)
#define BUFSZ_(NJ) (ATILE + 2 * BTILE_(NJ))
#define SMEM_GT8 (2 * BUFSZ_(8))
#define SMEM_GT4 (2 * BUFSZ_(4))

template<int NJ>
__global__ void __launch_bounds__(256, 1) gemm_tc_mma(
    const __half* __restrict__ A,
    const __half* __restrict__ Bh, const __half* __restrict__ Bl,
    const float* __restrict__ bias, float* __restrict__ Cout,
    int M, int N, int K, int mode)
{
    extern __shared__ char smc[];
    const uint32_t sbase = smem_u32(smc);
    const int tid  = threadIdx.x;
    const int lane = tid & 31;
    const int wid  = tid >> 5;
    const int wm   = wid & 1;
    const int wn   = wid >> 1;
    const int bm = blockIdx.y * 128;
    const int bn = blockIdx.x * (32 * NJ);

    const char* gA = (const char*)(A + (size_t)bm * K);
    const char* gB[2] = { (const char*)(Bh + (size_t)bn * K),
                          (const char*)(Bl + (size_t)bn * K) };

    const int nk = K / 64;

    auto aoff = [&](int buf) { return buf * BUFSZ_(NJ); };
    auto boff = [&](int buf, int v) { return buf * BUFSZ_(NJ) + ATILE + v * BTILE_(NJ); };

    auto issue_chunk = [&](int k0, int buf) {
#pragma unroll
        for (int j = 0; j < 4; j++) {
            const int idx = j * 256 + tid;
            const int row = idx >> 3, c16 = idx & 7;
            cp16(sbase + aoff(buf) + row * LDKB + c16 * 16,
                 gA + (size_t)row * (K * 2) + k0 * 2 + c16 * 16);
        }
#pragma unroll
        for (int v = 0; v < 2; v++)
#pragma unroll
            for (int j = 0; j < NJ; j++) {
                const int idx = j * 256 + tid;
                const int row = idx >> 3, c16 = idx & 7;
                cp16(sbase + boff(buf, v) + row * LDKB + c16 * 16,
                     gB[v] + (size_t)row * (K * 2) + k0 * 2 + c16 * 16);
            }
    };

    issue_chunk(0, 0); CP_COMMIT();
    if (nk > 1) { issue_chunk(64, 1); }
    CP_COMMIT();

    float acc[4][NJ][4];
#pragma unroll
    for (int i = 0; i < 4; i++)
#pragma unroll
        for (int j = 0; j < NJ; j++)
#pragma unroll
            for (int q = 0; q < 4; q++) acc[i][j][q] = 0.f;

    const int lr = lane >> 2;
    const int lc = (lane & 3) * 2;

    const uint32_t aLane = (((lane >> 3) & 1) * 8 + (lane & 7)) * LDKB + (lane >> 4) * 16;
    const uint32_t bLane = ((lane >> 4) * 8 + (lane & 7)) * LDKB + ((lane >> 3) & 1) * 16;

    for (int it = 0; it < nk; ++it) {
        const int buf = it & 1;
        CP_WAIT1();
        __syncthreads();

        const uint32_t sA = sbase + (uint32_t)aoff(buf);
        const uint32_t sB[2] = { sbase + (uint32_t)boff(buf, 0), sbase + (uint32_t)boff(buf, 1) };

#pragma unroll
        for (int kk = 0; kk < 4; kk++) {
            uint32_t af[4][4];
#pragma unroll
            for (int i = 0; i < 4; i++)
                ldsm4(af[i][0], af[i][1], af[i][2], af[i][3],
                      sA + (wm * 64 + i * 16) * LDKB + aLane + kk * 32);
            uint32_t bf[2][NJ][2];
#pragma unroll
            for (int v = 0; v < 2; v++)
#pragma unroll
                for (int jp = 0; jp < NJ / 2; jp++)
                    ldsm4(bf[v][2 * jp][0], bf[v][2 * jp][1],
                          bf[v][2 * jp + 1][0], bf[v][2 * jp + 1][1],
                          sB[v] + (wn * (8 * NJ) + jp * 16) * LDKB + bLane + kk * 32);
#pragma unroll
            for (int i = 0; i < 4; i++)
#pragma unroll
                for (int j = 0; j < NJ; j++)
                    mma16816h(acc[i][j], af[i], bf[0][j]);
#pragma unroll
            for (int i = 0; i < 4; i++)
#pragma unroll
                for (int j = 0; j < NJ; j++)
                    mma16816h(acc[i][j], af[i], bf[1][j]);
        }
        __syncthreads();
        if (it + 2 < nk) { issue_chunk((it + 2) * 64, buf); }
        CP_COMMIT();
    }

    // -------- epilogue --------
#pragma unroll
    for (int i = 0; i < 4; i++) {
        const int row0 = bm + wm * 64 + i * 16 + lr;
#pragma unroll
        for (int j = 0; j < NJ; j++) {
            const int col = bn + wn * (8 * NJ) + j * 8 + lc;
            const float b0 = bias[col], b1 = bias[col + 1];
            const float v00 = acc[i][j][0] + b0, v01 = acc[i][j][1] + b1;
            const float v10 = acc[i][j][2] + b0, v11 = acc[i][j][3] + b1;
            if (mode == 1) {
                *(float2*)&Cout[(size_t)row0 * N + col]       = make_float2(v00, v01);
                *(float2*)&Cout[(size_t)(row0 + 8) * N + col] = make_float2(v10, v11);
            } else {
                const int sel = col / D_;
                const int rem = col % D_;
                const int h   = rem / HD_;
                const int d0  = rem % HD_;
                const int bb0 = row0 >> 12, t0 = row0 & (T_ - 1);
                const int bb1 = (row0 + 8) >> 12, t1 = (row0 + 8) & (T_ - 1);
                if (sel == 2) {
                    const size_t hb0 = (size_t)(bb0 * H_ + h) * HD_;
                    const size_t hb1 = (size_t)(bb1 * H_ + h) * HD_;
                    __half h00 = __float2half_rn(v00);
                    __half h01 = __float2half_rn(v01);
                    __half h10 = __float2half_rn(v10);
                    __half h11 = __float2half_rn(v11);
                    g_vh[(hb0 + d0)     * T_ + t0] = h00;
                    g_vh[(hb0 + d0 + 1) * T_ + t0] = h01;
                    g_vh[(hb1 + d0)     * T_ + t1] = h10;
                    g_vh[(hb1 + d0 + 1) * T_ + t1] = h11;
                    g_vl[(hb0 + d0)     * T_ + t0] = __float2half_rn(v00 - __half2float(h00));
                    g_vl[(hb0 + d0 + 1) * T_ + t0] = __float2half_rn(v01 - __half2float(h01));
                    g_vl[(hb1 + d0)     * T_ + t1] = __float2half_rn(v10 - __half2float(h10));
                    g_vl[(hb1 + d0 + 1) * T_ + t1] = __float2half_rn(v11 - __half2float(h11));
                } else if (sel == 0) {
                    size_t off = ((size_t)(bb0 * H_ + h) * T_ + t0) * HD_ + d0;
                    *(uint32_t*)&g_qh[off] = pack_h(v00, v01);
                    off = ((size_t)(bb1 * H_ + h) * T_ + t1) * HD_ + d0;
                    *(uint32_t*)&g_qh[off] = pack_h(v10, v11);
                } else {
                    uint32_t hi, lo;
                    split2h(v00, v01, hi, lo);
                    size_t off = ((size_t)(bb0 * H_ + h) * T_ + t0) * HD_ + d0;
                    *(uint32_t*)&g_kh[off] = hi; *(uint32_t*)&g_kl[off] = lo;
                    split2h(v10, v11, hi, lo);
                    off = ((size_t)(bb1 * H_ + h) * T_ + t1) * HD_ + d0;
                    *(uint32_t*)&g_kh[off] = hi; *(uint32_t*)&g_kl[off] = lo;
                }
            }
        }
    }
    CP_WAIT0();
}

// ======================================================================
// Causal flash attention, fp16 2-product (unchanged from round 16
// passing version except epilogue writes single fp16 to g_a16).
// ======================================================================
#define APB 144
#define AT_KV (64 * APB)                 // 9216 (Q hi only)
#define KVBUF (4 * 64 * APB)             // 36864 per ring slot
#define SMEM_AT (AT_KV + 2 * KVBUF)      // 82944

__global__ void __launch_bounds__(128, 2) attn_mma()
{
    extern __shared__ char sm[];
    const uint32_t sbase = smem_u32(sm);
    char* sQh = sm;

    const int tid = threadIdx.x, lane = tid & 31, wid = tid >> 5;
    const int lr = lane >> 2, lq = lane & 3;
    const int qi = (int)gridDim.x - 1 - (int)blockIdx.x;
    const int h = blockIdx.y, b = blockIdx.z;
    const int qbase = qi * QT;

    const size_t bh = (size_t)(b * H_ + h) * T_;
    const char* qh = (const char*)(g_qh + (bh + qbase) * HD_);
    const char* kh = (const char*)(g_kh + bh * HD_);
    const char* kl = (const char*)(g_kl + bh * HD_);
    const char* vh = (const char*)(g_vh + bh * HD_);
    const char* vl = (const char*)(g_vl + bh * HD_);

    auto stage = [&](int kb, int buf) {
        const uint32_t base = sbase + AT_KV + buf * KVBUF;
#pragma unroll
        for (int t = 0; t < 4; t++) {
            const char* src = (t == 0) ? kh : (t == 1) ? kl : (t == 2) ? vh : vl;
#pragma unroll
            for (int j = 0; j < 4; j++) {
                const int idx = j * 128 + tid;
                const int row = idx >> 3, c16 = idx & 7;
                const char* g = (t < 2)
                    ? src + (size_t)(kb + row) * 128 + c16 * 16
                    : src + (size_t)row * (T_ * 2) + (size_t)kb * 2 + c16 * 16;
                cp16(base + t * (64 * APB) + row * APB + c16 * 16, g);
            }
        }
    };

    const int nkt = qi + 1;

    stage(0, 0); CP_COMMIT();

#pragma unroll
    for (int p = 0; p < 4; p++) {
        const int idx = p * 128 + tid;
        const int row = idx >> 3, c16 = idx & 7;
        *(uint4*)(sQh + row * APB + c16 * 16) =
            *(const uint4*)(qh + (size_t)row * 128 + c16 * 16);
    }
    __syncthreads();

    uint32_t qf[4][4];
    {
        const int r0 = (wid * 16 + lr) * APB;
#pragma unroll
        for (int kk = 0; kk < 4; kk++) {
            const int kbo = kk * 32 + lq * 4;
            qf[kk][0] = *(const uint32_t*)(sQh + r0 + kbo);
            qf[kk][1] = *(const uint32_t*)(sQh + r0 + 8 * APB + kbo);
            qf[kk][2] = *(const uint32_t*)(sQh + r0 + kbo + 16);
            qf[kk][3] = *(const uint32_t*)(sQh + r0 + 8 * APB + kbo + 16);
        }
    }

    float m[2] = {-1e30f, -1e30f}, l[2] = {0.f, 0.f};
    float o[8][4];
#pragma unroll
    for (int j = 0; j < 8; j++)
#pragma unroll
        for (int q = 0; q < 4; q++) o[j][q] = 0.f;

    const uint32_t kvLane = ((lane >> 4) * 8 + (lane & 7)) * APB + ((lane >> 3) & 1) * 16;

    uint32_t bfh[2][8][2], bfl[2][8][2];

    for (int kt = 0; kt < nkt; kt++) {
        const int kb = kt * QT;
        const int buf = kt & 1;
        const uint32_t kB  = sbase + AT_KV + buf * KVBUF;
        const uint32_t klB = kB  + 64 * APB;
        const uint32_t vB  = klB + 64 * APB;
        const uint32_t vlB = vB  + 64 * APB;

        CP_WAIT0();
        __syncthreads();
        if (kt + 1 < nkt) stage((kt + 1) * QT, (kt + 1) & 1);
        CP_COMMIT();

        float s[8][4];
#pragma unroll
        for (int j = 0; j < 8; j++)
#pragma unroll
            for (int q = 0; q < 4; q++) s[j][q] = 0.f;

        auto loadK = [&](int kk, int pb) {
#pragma unroll
            for (int jp = 0; jp < 4; jp++) {
                ldsm4(bfh[pb][2 * jp][0], bfh[pb][2 * jp][1],
                      bfh[pb][2 * jp + 1][0], bfh[pb][2 * jp + 1][1],
                      kB + jp * 16 * APB + kvLane + kk * 32);
                ldsm4(bfl[pb][2 * jp][0], bfl[pb][2 * jp][1],
                      bfl[pb][2 * jp + 1][0], bfl[pb][2 * jp + 1][1],
                      klB + jp * 16 * APB + kvLane + kk * 32);
            }
        };

        loadK(0, 0);
#pragma unroll
        for (int kk = 0; kk < 4; kk++) {
            const int pb = kk & 1;
            if (kk < 3) loadK(kk + 1, pb ^ 1);
#pragma unroll
            for (int j = 0; j < 8; j++) mma16816h(s[j], qf[kk], bfh[pb][j]);
#pragma unroll
            for (int j = 0; j < 8; j++) mma16816h(s[j], qf[kk], bfl[pb][j]);
        }

        const bool needmask = (kb + 63) > (qbase + wid * 16);
        if (needmask) {
            const int row_a = qbase + wid * 16 + lr;
#pragma unroll
            for (int j = 0; j < 8; j++) {
                const int col0 = kb + j * 8 + lq * 2;
                s[j][0] = (col0     <= row_a)     ? s[j][0] * SCALE2_ : -1e30f;
                s[j][1] = (col0 + 1 <= row_a)     ? s[j][1] * SCALE2_ : -1e30f;
                s[j][2] = (col0     <= row_a + 8) ? s[j][2] * SCALE2_ : -1e30f;
                s[j][3] = (col0 + 1 <= row_a + 8) ? s[j][3] * SCALE2_ : -1e30f;
            }
        } else {
#pragma unroll
            for (int j = 0; j < 8; j++)
#pragma unroll
                for (int q = 0; q < 4; q++) s[j][q] *= SCALE2_;
        }

#pragma unroll
        for (int r = 0; r < 2; r++) {
            float mx = -1e30f;
#pragma unroll
            for (int j = 0; j < 8; j++)
                mx = fmaxf(mx, fmaxf(s[j][2 * r], s[j][2 * r + 1]));
            mx = fmaxf(mx, __shfl_xor_sync(0xffffffffu, mx, 1));
            mx = fmaxf(mx, __shfl_xor_sync(0xffffffffu, mx, 2));
            const float mnew = fmaxf(m[r], mx);
            const float corr = ex2(m[r] - mnew);
            float sum = 0.f;
#pragma unroll
            for (int j = 0; j < 8; j++) {
                const float p0 = ex2(s[j][2 * r]     - mnew);
                const float p1 = ex2(s[j][2 * r + 1] - mnew);
                s[j][2 * r] = p0; s[j][2 * r + 1] = p1;
                sum += p0 + p1;
            }
            sum += __shfl_xor_sync(0xffffffffu, sum, 1);
            sum += __shfl_xor_sync(0xffffffffu, sum, 2);
            l[r] = l[r] * corr + sum;
            m[r] = mnew;
#pragma unroll
            for (int j = 0; j < 8; j++) {
                o[j][2 * r] *= corr; o[j][2 * r + 1] *= corr;
            }
        }

        uint32_t ph0[8], ph1[8];
#pragma unroll
        for (int j = 0; j < 8; j++) {
            ph0[j] = pack_h(s[j][0], s[j][1]);
            ph1[j] = pack_h(s[j][2], s[j][3]);
        }

        auto loadV = [&](int kk, int pb) {
#pragma unroll
            for (int jp = 0; jp < 4; jp++) {
                ldsm4(bfh[pb][2 * jp][0], bfh[pb][2 * jp][1],
                      bfh[pb][2 * jp + 1][0], bfh[pb][2 * jp + 1][1],
                      vB + jp * 16 * APB + kvLane + kk * 32);
                ldsm4(bfl[pb][2 * jp][0], bfl[pb][2 * jp][1],
                      bfl[pb][2 * jp + 1][0], bfl[pb][2 * jp + 1][1],
                      vlB + jp * 16 * APB + kvLane + kk * 32);
            }
        };

        loadV(0, 0);
#pragma unroll
        for (int kk = 0; kk < 4; kk++) {
            const int pb = kk & 1;
            if (kk < 3) loadV(kk + 1, pb ^ 1);
            uint32_t a_h[4] = { ph0[2 * kk], ph1[2 * kk], ph0[2 * kk + 1], ph1[2 * kk + 1] };
#pragma unroll
            for (int jn = 0; jn < 8; jn++) mma16816h(o[jn], a_h, bfh[pb][jn]);
#pragma unroll
            for (int jn = 0; jn < 8; jn++) mma16816h(o[jn], a_h, bfl[pb][jn]);
        }
    }

    // ---- epilogue: normalize, single fp16 write to g_a16 [B,T,D] ----
    const float inv0 = 1.f / l[0], inv1 = 1.f / l[1];
    const int t0 = qbase + wid * 16 + lr;
    const int t1 = t0 + 8;
#pragma unroll
    for (int jn = 0; jn < 8; jn++) {
        const int d = h * HD_ + jn * 8 + lq * 2;
        size_t off = (size_t)(b * T_ + t0) * D_ + d;
        *(uint32_t*)&g_a16[off] = pack_h(o[jn][0] * inv0, o[jn][1] * inv0);
        off = (size_t)(b * T_ + t1) * D_ + d;
        *(uint32_t*)&g_a16[off] = pack_h(o[jn][2] * inv1, o[jn][3] * inv1);
    }
    CP_WAIT0();
}

// ======================================================================
extern "C" void kernel_launch(void* const* d_in, const int* in_sizes, int n_in,
                              void* d_out, int out_size)
{
    const float* x      = (const float*)d_in[0];
    const float* W_qkv  = (const float*)d_in[1];
    const float* b_qkv  = (const float*)d_in[2];
    const float* W_out  = (const float*)d_in[3];
    const float* b_out  = (const float*)d_in[4];
    float* out = (float*)d_out;

    __half *x16, *a16, *wqh, *wql, *woh, *wol;
    cudaGetSymbolAddress((void**)&x16, g_x16);
    cudaGetSymbolAddress((void**)&a16, g_a16);
    cudaGetSymbolAddress((void**)&wqh, g_wqh);
    cudaGetSymbolAddress((void**)&wql, g_wql);
    cudaGetSymbolAddress((void**)&woh, g_woh);
    cudaGetSymbolAddress((void**)&wol, g_wol);

    cudaFuncSetAttribute(gemm_tc_mma<8>, cudaFuncAttributeMaxDynamicSharedMemorySize, SMEM_GT8);
    cudaFuncSetAttribute(gemm_tc_mma<4>, cudaFuncAttributeMaxDynamicSharedMemorySize, SMEM_GT4);
    cudaFuncSetAttribute(attn_mma,       cudaFuncAttributeMaxDynamicSharedMemorySize, SMEM_AT);

    const int nX = B_ * T_ * D_;

    conv_h<<<(nX + 255) / 256, 256>>>(x, x16, nX);
    {
        dim3 blk(32, 8);
        dim3 g1((3 * D_) / 32, D_ / 32);
        conv_split_tr<<<g1, blk>>>(W_qkv, wqh, wql, D_, 3 * D_);
        dim3 g2(D_ / 32, D_ / 32);
        conv_split_tr<<<g2, blk>>>(W_out, woh, wol, D_, D_);
    }

    // 1) QKV projection (fp16 2-product, N-tile 256)
    {
        dim3 grid((3 * D_) / 256, (B_ * T_) / 128);
        gemm_tc_mma<8><<<grid, 256, SMEM_GT8>>>(x16, wqh, wql, b_qkv, nullptr,
                                                B_ * T_, 3 * D_, D_, 0);
    }
    // 2) causal flash attention (fp16 2-product, QT=64, 2 CTAs/SM)
    {
        dim3 grid(T_ / QT, H_, B_);
        attn_mma<<<grid, 128, SMEM_AT>>>();
    }
    // 3) output projection (fp16 2-product, N-tile 128)
    {
        dim3 grid(D_ / 128, (B_ * T_) / 128);
        gemm_tc_mma<4><<<grid, 256, SMEM_GT4>>>(a16, woh, wol, b_out, out,
                                                B_ * T_, D_, D_, 1);
    }
}